// round 2
// baseline (speedup 1.0000x reference)
#include <cuda_runtime.h>
#include <math.h>

// Problem constants
#define Bz   8
#define Lz   1025
#define Ez   384
#define Hz   6
#define Dz   64
#define WINz 33
#define PADz 16
#define Mz   (Bz * Lz)          // 8200 rows
#define SCALE 0.125f            // 1/sqrt(64)

// Scratch (device globals; no runtime allocation allowed)
__device__ float g_Q[Bz * Hz * Lz * Dz];
__device__ float g_K[Bz * Hz * Lz * Dz];
__device__ float g_V[Bz * Hz * Lz * Dz];
__device__ float g_attn[Bz * Lz * Ez];

// ---------------------------------------------------------------------------
// Fused QKV projection GEMM: for z = blockIdx.z in {0,1,2}:
//   P = x(M,K) @ W[z](K,N) + b[z](N), scattered to g_Q/g_K/g_V in (B,H,L,D).
// BM=BN=128, BK=8, 256 threads, 8x8 per thread.
// ---------------------------------------------------------------------------
__global__ __launch_bounds__(256) void qkv_gemm_kernel(
    const float* __restrict__ A,
    const float* __restrict__ Wq, const float* __restrict__ bq,
    const float* __restrict__ Wk, const float* __restrict__ bk,
    const float* __restrict__ Wv, const float* __restrict__ bv)
{
    __shared__ float As[8][128];
    __shared__ float Bs[8][128];

    const int tid = threadIdx.x;
    const int bm = blockIdx.y;
    const int bn = blockIdx.x;
    const int z  = blockIdx.z;

    const float* W    = (z == 0) ? Wq : (z == 1) ? Wk : Wv;
    const float* bias = (z == 0) ? bq : (z == 1) ? bk : bv;
    float*       dst  = (z == 0) ? g_Q : (z == 1) ? g_K : g_V;

    const int aRow = tid >> 1;
    const int aCol = (tid & 1) * 4;
    const int bRow = tid >> 5;
    const int bCol = (tid & 31) * 4;
    const int tRow = (tid >> 4) * 8;
    const int tCol = (tid & 15) * 8;

    float acc[8][8];
#pragma unroll
    for (int i = 0; i < 8; ++i)
#pragma unroll
        for (int j = 0; j < 8; ++j) acc[i][j] = 0.f;

    const int gARow = bm * 128 + aRow;
    const bool aValid = (gARow < Mz);
    const float* Ap = A + (size_t)gARow * Ez + aCol;
    const float* Wp = W + (size_t)bRow * Ez + bn * 128 + bCol;

    for (int k0 = 0; k0 < Ez; k0 += 8) {
        float4 av = make_float4(0.f, 0.f, 0.f, 0.f);
        if (aValid) av = *(const float4*)(Ap + k0);
        As[aCol + 0][aRow] = av.x;
        As[aCol + 1][aRow] = av.y;
        As[aCol + 2][aRow] = av.z;
        As[aCol + 3][aRow] = av.w;

        float4 bv4 = *(const float4*)(Wp + (size_t)k0 * Ez);
        *(float4*)&Bs[bRow][bCol] = bv4;

        __syncthreads();

#pragma unroll
        for (int k = 0; k < 8; ++k) {
            float ra[8], rb[8];
#pragma unroll
            for (int i = 0; i < 8; ++i) ra[i] = As[k][tRow + i];
#pragma unroll
            for (int j = 0; j < 8; ++j) rb[j] = Bs[k][tCol + j];
#pragma unroll
            for (int i = 0; i < 8; ++i)
#pragma unroll
                for (int j = 0; j < 8; ++j) acc[i][j] = fmaf(ra[i], rb[j], acc[i][j]);
        }
        __syncthreads();
    }

#pragma unroll
    for (int i = 0; i < 8; ++i) {
        int row = bm * 128 + tRow + i;
        if (row >= Mz) continue;
        int b = row / Lz, l = row - b * Lz;
#pragma unroll
        for (int j = 0; j < 8; ++j) {
            int col = bn * 128 + tCol + j;
            float v = acc[i][j] + bias[col];
            int h = col >> 6, d = col & 63;
            dst[(((size_t)(b * Hz + h)) * Lz + l) * Dz + d] = v;
        }
    }
}

// ---------------------------------------------------------------------------
// Output projection GEMM: out = g_attn(M,E) @ Wo(E,E) + bo.
// g_attn referenced as device symbol INSIDE the kernel (never from host!).
// ---------------------------------------------------------------------------
__global__ __launch_bounds__(256) void out_gemm_kernel(
    const float* __restrict__ W, const float* __restrict__ bias,
    float* __restrict__ Cout)
{
    __shared__ float As[8][128];
    __shared__ float Bs[8][128];

    const float* A = (const float*)g_attn;   // device-side symbol address

    const int tid = threadIdx.x;
    const int bm = blockIdx.y;
    const int bn = blockIdx.x;

    const int aRow = tid >> 1;
    const int aCol = (tid & 1) * 4;
    const int bRow = tid >> 5;
    const int bCol = (tid & 31) * 4;
    const int tRow = (tid >> 4) * 8;
    const int tCol = (tid & 15) * 8;

    float acc[8][8];
#pragma unroll
    for (int i = 0; i < 8; ++i)
#pragma unroll
        for (int j = 0; j < 8; ++j) acc[i][j] = 0.f;

    const int gARow = bm * 128 + aRow;
    const bool aValid = (gARow < Mz);
    const float* Ap = A + (size_t)gARow * Ez + aCol;
    const float* Wp = W + (size_t)bRow * Ez + bn * 128 + bCol;

    for (int k0 = 0; k0 < Ez; k0 += 8) {
        float4 av = make_float4(0.f, 0.f, 0.f, 0.f);
        if (aValid) av = *(const float4*)(Ap + k0);
        As[aCol + 0][aRow] = av.x;
        As[aCol + 1][aRow] = av.y;
        As[aCol + 2][aRow] = av.z;
        As[aCol + 3][aRow] = av.w;

        float4 bv4 = *(const float4*)(Wp + (size_t)k0 * Ez);
        *(float4*)&Bs[bRow][bCol] = bv4;

        __syncthreads();

#pragma unroll
        for (int k = 0; k < 8; ++k) {
            float ra[8], rb[8];
#pragma unroll
            for (int i = 0; i < 8; ++i) ra[i] = As[k][tRow + i];
#pragma unroll
            for (int j = 0; j < 8; ++j) rb[j] = Bs[k][tCol + j];
#pragma unroll
            for (int i = 0; i < 8; ++i)
#pragma unroll
                for (int j = 0; j < 8; ++j) acc[i][j] = fmaf(ra[i], rb[j], acc[i][j]);
        }
        __syncthreads();
    }

#pragma unroll
    for (int i = 0; i < 8; ++i) {
        int row = bm * 128 + tRow + i;
        if (row >= Mz) continue;
#pragma unroll
        for (int j = 0; j < 8; ++j) {
            int col = bn * 128 + tCol + j;
            Cout[(size_t)row * Ez + col] = acc[i][j] + bias[col];
        }
    }
}

// ---------------------------------------------------------------------------
// CLS attention: query l=0 attends to all L keys. One block per (h, b).
// ---------------------------------------------------------------------------
__global__ __launch_bounds__(256) void cls_attn_kernel()
{
    const int h = blockIdx.x;
    const int b = blockIdx.y;
    const int tid = threadIdx.x;

    __shared__ float qv[Dz];
    __shared__ float sc[Lz];
    __shared__ float red[256];

    const size_t base = ((size_t)(b * Hz + h)) * Lz * Dz;
    const float* Qp = g_Q + base;
    const float* Kp = g_K + base;
    const float* Vp = g_V + base;

    if (tid < Dz) qv[tid] = Qp[tid];
    __syncthreads();

    float lmax = -INFINITY;
    for (int k = tid; k < Lz; k += 256) {
        const float* kr = Kp + (size_t)k * Dz;
        float s = 0.f;
#pragma unroll 16
        for (int d = 0; d < Dz; ++d) s = fmaf(qv[d], kr[d], s);
        s *= SCALE;
        sc[k] = s;
        lmax = fmaxf(lmax, s);
    }
    red[tid] = lmax;
    __syncthreads();
    for (int s2 = 128; s2 > 0; s2 >>= 1) {
        if (tid < s2) red[tid] = fmaxf(red[tid], red[tid + s2]);
        __syncthreads();
    }
    const float m = red[0];
    __syncthreads();

    float lsum = 0.f;
    for (int k = tid; k < Lz; k += 256) {
        float p = __expf(sc[k] - m);
        sc[k] = p;
        lsum += p;
    }
    red[tid] = lsum;
    __syncthreads();
    for (int s2 = 128; s2 > 0; s2 >>= 1) {
        if (tid < s2) red[tid] += red[tid + s2];
        __syncthreads();
    }
    const float inv = 1.f / red[0];

    if (tid < Dz) {
        float a0 = 0.f, a1 = 0.f, a2 = 0.f, a3 = 0.f;
        int k = 0;
        for (; k + 3 < Lz; k += 4) {
            a0 = fmaf(sc[k + 0], Vp[(size_t)(k + 0) * Dz + tid], a0);
            a1 = fmaf(sc[k + 1], Vp[(size_t)(k + 1) * Dz + tid], a1);
            a2 = fmaf(sc[k + 2], Vp[(size_t)(k + 2) * Dz + tid], a2);
            a3 = fmaf(sc[k + 3], Vp[(size_t)(k + 3) * Dz + tid], a3);
        }
        for (; k < Lz; ++k) a0 = fmaf(sc[k], Vp[(size_t)k * Dz + tid], a0);
        float acc = (a0 + a1) + (a2 + a3);
        g_attn[((size_t)b * Lz + 0) * Ez + h * Dz + tid] = acc * inv;
    }
}

// ---------------------------------------------------------------------------
// Windowed attention for queries l=1..L-1.
// Block = (qtile of 32, h, b). 256 threads = 8 warps, 4 queries per warp.
// ---------------------------------------------------------------------------
__global__ __launch_bounds__(256) void win_attn_kernel()
{
    const int bx = blockIdx.x;
    const int h  = blockIdx.y;
    const int b  = blockIdx.z;
    const int tid = threadIdx.x;

    __shared__ float Ks[65][64];
    __shared__ float Vs[65][64];

    const int q0 = 1 + bx * 32;
    const size_t bhbase = ((size_t)(b * Hz + h)) * Lz * Dz;
    const float* Kbase = g_K + bhbase;
    const float* Vbase = g_V + bhbase;

    for (int i = tid; i < 65 * 16; i += 256) {
        int r = i >> 4;
        int c = (i & 15) * 4;
        int kidx = (r == 64) ? 0 : (q0 - 16 + r);
        float4 kv = make_float4(0.f, 0.f, 0.f, 0.f);
        float4 vv = kv;
        if (kidx >= 0 && kidx < Lz) {
            kv = *(const float4*)(Kbase + (size_t)kidx * Dz + c);
            vv = *(const float4*)(Vbase + (size_t)kidx * Dz + c);
        }
        *(float4*)&Ks[r][c] = kv;
        *(float4*)&Vs[r][c] = vv;
    }
    __syncthreads();

    const int warp = tid >> 5;
    const int lane = tid & 31;
    const unsigned FULL = 0xffffffffu;

    for (int i = 0; i < 4; ++i) {
        const int l = q0 + warp * 4 + i;
        const int base = l - q0;
        const float qv0 = g_Q[bhbase + (size_t)l * Dz + lane];
        const float qv1 = g_Q[bhbase + (size_t)l * Dz + lane + 32];

        float s_lo = -INFINITY;
        float s_hi = -INFINITY;

#pragma unroll
        for (int w = 0; w < 33; ++w) {
            int row = base + w;
            float v = qv0 * Ks[row][lane] + qv1 * Ks[row][lane + 32];
            v += __shfl_xor_sync(FULL, v, 16);
            v += __shfl_xor_sync(FULL, v, 8);
            v += __shfl_xor_sync(FULL, v, 4);
            v += __shfl_xor_sync(FULL, v, 2);
            v += __shfl_xor_sync(FULL, v, 1);
            int kidx = l - PADz + w;
            float scv = (kidx >= 1 && kidx < Lz) ? v * SCALE : -INFINITY;
            if (w < 32) {
                if (lane == w) s_lo = scv;
            } else {
                if (lane == 0) s_hi = scv;
            }
        }
        {
            float v = qv0 * Ks[64][lane] + qv1 * Ks[64][lane + 32];
            v += __shfl_xor_sync(FULL, v, 16);
            v += __shfl_xor_sync(FULL, v, 8);
            v += __shfl_xor_sync(FULL, v, 4);
            v += __shfl_xor_sync(FULL, v, 2);
            v += __shfl_xor_sync(FULL, v, 1);
            if (lane == 1) s_hi = v * SCALE;
        }

        float m = fmaxf(s_lo, s_hi);
        m = fmaxf(m, __shfl_xor_sync(FULL, m, 16));
        m = fmaxf(m, __shfl_xor_sync(FULL, m, 8));
        m = fmaxf(m, __shfl_xor_sync(FULL, m, 4));
        m = fmaxf(m, __shfl_xor_sync(FULL, m, 2));
        m = fmaxf(m, __shfl_xor_sync(FULL, m, 1));

        float p_lo = __expf(s_lo - m);
        float p_hi = (lane < 2) ? __expf(s_hi - m) : 0.f;
        float t = p_lo + p_hi;
        t += __shfl_xor_sync(FULL, t, 16);
        t += __shfl_xor_sync(FULL, t, 8);
        t += __shfl_xor_sync(FULL, t, 4);
        t += __shfl_xor_sync(FULL, t, 2);
        t += __shfl_xor_sync(FULL, t, 1);
        const float inv = 1.f / t;

        float acc0 = 0.f, acc1 = 0.f;
#pragma unroll
        for (int w = 0; w < 32; ++w) {
            float p = __shfl_sync(FULL, p_lo, w);
            int row = base + w;
            acc0 = fmaf(p, Vs[row][lane],      acc0);
            acc1 = fmaf(p, Vs[row][lane + 32], acc1);
        }
        {
            float p32 = __shfl_sync(FULL, p_hi, 0);
            acc0 = fmaf(p32, Vs[base + 32][lane],      acc0);
            acc1 = fmaf(p32, Vs[base + 32][lane + 32], acc1);
            float pc = __shfl_sync(FULL, p_hi, 1);
            acc0 = fmaf(pc, Vs[64][lane],      acc0);
            acc1 = fmaf(pc, Vs[64][lane + 32], acc1);
        }

        float* op = g_attn + ((size_t)b * Lz + l) * Ez + h * Dz;
        op[lane]      = acc0 * inv;
        op[lane + 32] = acc1 * inv;
    }
}

// ---------------------------------------------------------------------------
// Launch
// ---------------------------------------------------------------------------
extern "C" void kernel_launch(void* const* d_in, const int* in_sizes, int n_in,
                              void* d_out, int out_size)
{
    const float* x  = (const float*)d_in[0];
    const float* Wq = (const float*)d_in[1];
    const float* bq = (const float*)d_in[2];
    const float* Wk = (const float*)d_in[3];
    const float* bk = (const float*)d_in[4];
    const float* Wv = (const float*)d_in[5];
    const float* bv = (const float*)d_in[6];
    const float* Wo = (const float*)d_in[7];
    const float* bo = (const float*)d_in[8];
    float* out = (float*)d_out;

    dim3 gridQKV(Ez / 128, (Mz + 127) / 128, 3);   // (3, 65, 3) = 585 blocks
    dim3 gridO(Ez / 128, (Mz + 127) / 128);        // (3, 65)
    dim3 blockG(256);

    qkv_gemm_kernel<<<gridQKV, blockG>>>(x, Wq, bq, Wk, bk, Wv, bv);

    cls_attn_kernel<<<dim3(Hz, Bz), 256>>>();
    win_attn_kernel<<<dim3(32, Hz, Bz), 256>>>();

    out_gemm_kernel<<<gridO, blockG>>>(Wo, bo, out);
}

// round 4
// speedup vs baseline: 1.4557x; 1.4557x over previous
#include <cuda_runtime.h>
#include <cuda_bf16.h>
#include <math.h>
#include <cstdint>

// Problem constants
#define Bz   8
#define Lz   1025
#define Ez   384
#define Hz   6
#define Dz   64
#define PADz 16
#define Mz   (Bz * Lz)          // 8200 rows
#define SCALE 0.125f

// Scratch (device globals; no runtime allocation allowed)
__device__ float g_Q[Bz * Hz * Lz * Dz];
__device__ float g_K[Bz * Hz * Lz * Dz];
__device__ float g_V[Bz * Hz * Lz * Dz];
__device__ float g_attn[Bz * Lz * Ez];

// ===========================================================================
// Warp-level tensor-core helpers (sm_80+ instructions; no 'a'-suffix features)
// ===========================================================================
__device__ __forceinline__ uint32_t smem_u32(const void* p) {
    uint32_t a;
    asm("{ .reg .u64 t; cvta.to.shared.u64 t, %1; cvt.u32.u64 %0, t; }"
        : "=r"(a) : "l"(p));
    return a;
}

__device__ __forceinline__ void ldsm_x4(uint32_t (&r)[4], uint32_t saddr) {
    asm volatile("ldmatrix.sync.aligned.m8n8.x4.shared.b16 {%0,%1,%2,%3}, [%4];"
        : "=r"(r[0]), "=r"(r[1]), "=r"(r[2]), "=r"(r[3]) : "r"(saddr));
}

__device__ __forceinline__ void mma_bf16(float (&c)[4], const uint32_t (&a)[4],
                                         uint32_t b0, uint32_t b1) {
    asm volatile(
        "mma.sync.aligned.m16n8k16.row.col.f32.bf16.bf16.f32 "
        "{%0,%1,%2,%3}, {%4,%5,%6,%7}, {%8,%9}, {%0,%1,%2,%3};"
        : "+f"(c[0]), "+f"(c[1]), "+f"(c[2]), "+f"(c[3])
        : "r"(a[0]), "r"(a[1]), "r"(a[2]), "r"(a[3]), "r"(b0), "r"(b1));
}

// fp32 pair -> packed bf16x2 (hi) and packed bf16x2 (residual lo)
__device__ __forceinline__ void split2(float x, float y, uint32_t& hi, uint32_t& lo)
{
    __nv_bfloat16 hx = __float2bfloat16(x);
    __nv_bfloat16 hy = __float2bfloat16(y);
    __nv_bfloat16 lx = __float2bfloat16(x - __bfloat162float(hx));
    __nv_bfloat16 ly = __float2bfloat16(y - __bfloat162float(hy));
    hi = (uint32_t)__bfloat16_as_ushort(hx) | ((uint32_t)__bfloat16_as_ushort(hy) << 16);
    lo = (uint32_t)__bfloat16_as_ushort(lx) | ((uint32_t)__bfloat16_as_ushort(ly) << 16);
}

#define KPAD 40   // 40 bf16 = 80 B row stride: 16B-aligned, conflict-free ldmatrix

// ===========================================================================
// HMMA GEMM: C(128x128 tile) = A(M,384) @ W(384,N) + bias, bf16x3 split.
// QKV=1: A = x, blockIdx.z selects Wq/Wk/Wv, scatter to g_Q/g_K/g_V (B,H,L,D)
// QKV=0: A = g_attn (device symbol), write Cout row-major
// 256 threads = 8 warps in 4(M) x 2(N): warp tile 32 x 64.
// ===========================================================================
template <int QKV>
__global__ __launch_bounds__(256) void mma_gemm_kernel(
    const float* __restrict__ A_,
    const float* __restrict__ W0, const float* __restrict__ b0,
    const float* __restrict__ W1, const float* __restrict__ b1,
    const float* __restrict__ W2, const float* __restrict__ b2,
    float* __restrict__ Cout)
{
    __shared__ __align__(16) __nv_bfloat16 As_hi[128][KPAD];
    __shared__ __align__(16) __nv_bfloat16 As_lo[128][KPAD];
    __shared__ __align__(16) __nv_bfloat16 Bs_hi[128][KPAD];
    __shared__ __align__(16) __nv_bfloat16 Bs_lo[128][KPAD];

    const int tid  = threadIdx.x;
    const int wid  = tid >> 5;
    const int lane = tid & 31;
    const int bn = blockIdx.x;
    const int bm = blockIdx.y;
    const int z  = QKV ? blockIdx.z : 0;

    const float* A    = QKV ? A_ : (const float*)g_attn;
    const float* W    = (z == 0) ? W0 : (z == 1) ? W1 : W2;
    const float* bias = (z == 0) ? b0 : (z == 1) ? b1 : b2;

    const int m0 = bm * 128;
    const int n0 = bn * 128;
    const int wm = wid & 3;      // 0..3 -> m offset wm*32
    const int wn = wid >> 2;     // 0..1 -> n offset wn*64

    const uint32_t sA_hi = smem_u32(As_hi);
    const uint32_t sA_lo = smem_u32(As_lo);
    const uint32_t sB_hi = smem_u32(Bs_hi);
    const uint32_t sB_lo = smem_u32(Bs_lo);

    float acc[2][8][4];
#pragma unroll
    for (int mt = 0; mt < 2; ++mt)
#pragma unroll
        for (int nt = 0; nt < 8; ++nt)
#pragma unroll
            for (int q = 0; q < 4; ++q) acc[mt][nt][q] = 0.f;

    const int grp = lane >> 3;     // ldmatrix address group 0..3
    const int wl  = lane & 7;

    for (int c = 0; c < 12; ++c) {      // K chunks of 32
        // ---- stage A chunk (128 x 32 fp32 -> bf16 hi/lo) ----
#pragma unroll
        for (int j = 0; j < 4; ++j) {
            int idx = tid + j * 256;            // 0..1023 (float4 granules)
            int r  = idx >> 3;                  // 0..127
            int c4 = (idx & 7) << 2;            // 0..28
            int grow = m0 + r;
            float4 v = make_float4(0.f, 0.f, 0.f, 0.f);
            if (grow < Mz)
                v = *(const float4*)(A + (size_t)grow * Ez + c * 32 + c4);
            uint32_t h01, l01, h23, l23;
            split2(v.x, v.y, h01, l01);
            split2(v.z, v.w, h23, l23);
            *(uint2*)&As_hi[r][c4] = make_uint2(h01, h23);
            *(uint2*)&As_lo[r][c4] = make_uint2(l01, l23);
        }
        // ---- stage B chunk: Bs[n][k] = W[c*32+k][n0+n] (k contiguous) ----
#pragma unroll
        for (int j = 0; j < 4; ++j) {
            int idx = tid + j * 256;            // 0..1023
            int n  = idx & 127;
            int kq = (idx >> 7) << 2;           // 0..28
            const float* wp = W + (size_t)(c * 32 + kq) * Ez + n0 + n;
            float f0 = wp[0];
            float f1 = wp[Ez];
            float f2 = wp[2 * Ez];
            float f3 = wp[3 * Ez];
            uint32_t h01, l01, h23, l23;
            split2(f0, f1, h01, l01);
            split2(f2, f3, h23, l23);
            *(uint2*)&Bs_hi[n][kq] = make_uint2(h01, h23);
            *(uint2*)&Bs_lo[n][kq] = make_uint2(l01, l23);
        }
        __syncthreads();

        // ---- compute: 2 k16 steps ----
#pragma unroll
        for (int ks = 0; ks < 2; ++ks) {
            const int k0 = ks * 16;

            // A fragments (m16k16 x2 m-tiles, hi & lo)
            uint32_t ah[2][4], al[2][4];
            const int a_r = wm * 32 + wl + (grp & 1) * 8;
            const int a_k = k0 + (grp >> 1) * 8;
#pragma unroll
            for (int mt = 0; mt < 2; ++mt) {
                uint32_t off = (uint32_t)((a_r + mt * 16) * KPAD + a_k) * 2;
                ldsm_x4(ah[mt], sA_hi + off);
                ldsm_x4(al[mt], sA_lo + off);
            }

            const int b_n = wn * 64 + wl + (grp >> 1) * 8;
            const int b_k = k0 + (grp & 1) * 8;
#pragma unroll
            for (int nt2 = 0; nt2 < 4; ++nt2) {
                uint32_t bh[4], bl[4];
                uint32_t off = (uint32_t)((b_n + nt2 * 16) * KPAD + b_k) * 2;
                ldsm_x4(bh, sB_hi + off);
                ldsm_x4(bl, sB_lo + off);
#pragma unroll
                for (int mt = 0; mt < 2; ++mt) {
                    mma_bf16(acc[mt][nt2 * 2 + 0], ah[mt], bh[0], bh[1]);
                    mma_bf16(acc[mt][nt2 * 2 + 0], ah[mt], bl[0], bl[1]);
                    mma_bf16(acc[mt][nt2 * 2 + 0], al[mt], bh[0], bh[1]);
                    mma_bf16(acc[mt][nt2 * 2 + 1], ah[mt], bh[2], bh[3]);
                    mma_bf16(acc[mt][nt2 * 2 + 1], ah[mt], bl[2], bl[3]);
                    mma_bf16(acc[mt][nt2 * 2 + 1], al[mt], bh[2], bh[3]);
                }
            }
        }
        __syncthreads();
    }

    // ---- epilogue: fragment -> gmem (float2 stores), bias add ----
    const int tq = lane >> 2;     // 0..7 (row in tile)
    const int tr = lane & 3;      // 0..3 (col pair)
#pragma unroll
    for (int mt = 0; mt < 2; ++mt) {
#pragma unroll
        for (int nt = 0; nt < 8; ++nt) {
            const int gcol = n0 + wn * 64 + nt * 8 + tr * 2;
            const float bv0 = bias[gcol];
            const float bv1 = bias[gcol + 1];
#pragma unroll
            for (int half = 0; half < 2; ++half) {
                const int grow = m0 + wm * 32 + mt * 16 + tq + half * 8;
                if (grow >= Mz) continue;
                float v0 = acc[mt][nt][half * 2 + 0] + bv0;
                float v1 = acc[mt][nt][half * 2 + 1] + bv1;
                if (QKV) {
                    int b = grow / Lz, l = grow - b * Lz;
                    int h = gcol >> 6, d = gcol & 63;
                    float* dst = (z == 0) ? g_Q : (z == 1) ? g_K : g_V;
                    *(float2*)(dst + (((size_t)(b * Hz + h)) * Lz + l) * Dz + d) =
                        make_float2(v0, v1);
                } else {
                    *(float2*)(Cout + (size_t)grow * Ez + gcol) = make_float2(v0, v1);
                }
            }
        }
    }
}

// ---------------------------------------------------------------------------
// CLS attention: query l=0 attends to all L keys. One block per (h, b).
// ---------------------------------------------------------------------------
__global__ __launch_bounds__(256) void cls_attn_kernel()
{
    const int h = blockIdx.x;
    const int b = blockIdx.y;
    const int tid = threadIdx.x;

    __shared__ float qv[Dz];
    __shared__ float sc[Lz];
    __shared__ float red[256];

    const size_t base = ((size_t)(b * Hz + h)) * Lz * Dz;
    const float* Qp = g_Q + base;
    const float* Kp = g_K + base;
    const float* Vp = g_V + base;

    if (tid < Dz) qv[tid] = Qp[tid];
    __syncthreads();

    float lmax = -INFINITY;
    for (int k = tid; k < Lz; k += 256) {
        const float* kr = Kp + (size_t)k * Dz;
        float s = 0.f;
#pragma unroll 16
        for (int d = 0; d < Dz; ++d) s = fmaf(qv[d], kr[d], s);
        s *= SCALE;
        sc[k] = s;
        lmax = fmaxf(lmax, s);
    }
    red[tid] = lmax;
    __syncthreads();
    for (int s2 = 128; s2 > 0; s2 >>= 1) {
        if (tid < s2) red[tid] = fmaxf(red[tid], red[tid + s2]);
        __syncthreads();
    }
    const float m = red[0];
    __syncthreads();

    float lsum = 0.f;
    for (int k = tid; k < Lz; k += 256) {
        float p = __expf(sc[k] - m);
        sc[k] = p;
        lsum += p;
    }
    red[tid] = lsum;
    __syncthreads();
    for (int s2 = 128; s2 > 0; s2 >>= 1) {
        if (tid < s2) red[tid] += red[tid + s2];
        __syncthreads();
    }
    const float inv = 1.f / red[0];

    if (tid < Dz) {
        float a0 = 0.f, a1 = 0.f, a2 = 0.f, a3 = 0.f;
        int k = 0;
        for (; k + 3 < Lz; k += 4) {
            a0 = fmaf(sc[k + 0], Vp[(size_t)(k + 0) * Dz + tid], a0);
            a1 = fmaf(sc[k + 1], Vp[(size_t)(k + 1) * Dz + tid], a1);
            a2 = fmaf(sc[k + 2], Vp[(size_t)(k + 2) * Dz + tid], a2);
            a3 = fmaf(sc[k + 3], Vp[(size_t)(k + 3) * Dz + tid], a3);
        }
        for (; k < Lz; ++k) a0 = fmaf(sc[k], Vp[(size_t)k * Dz + tid], a0);
        float acc = (a0 + a1) + (a2 + a3);
        g_attn[((size_t)b * Lz + 0) * Ez + h * Dz + tid] = acc * inv;
    }
}

// ---------------------------------------------------------------------------
// Windowed attention for queries l=1..L-1.
// Block = (qtile of 32, h, b). 256 threads = 8 warps, 4 queries per warp.
// ---------------------------------------------------------------------------
__global__ __launch_bounds__(256) void win_attn_kernel()
{
    const int bx = blockIdx.x;
    const int h  = blockIdx.y;
    const int b  = blockIdx.z;
    const int tid = threadIdx.x;

    __shared__ float Ks[65][64];
    __shared__ float Vs[65][64];

    const int q0 = 1 + bx * 32;
    const size_t bhbase = ((size_t)(b * Hz + h)) * Lz * Dz;
    const float* Kbase = g_K + bhbase;
    const float* Vbase = g_V + bhbase;

    for (int i = tid; i < 65 * 16; i += 256) {
        int r = i >> 4;
        int c = (i & 15) * 4;
        int kidx = (r == 64) ? 0 : (q0 - 16 + r);
        float4 kv = make_float4(0.f, 0.f, 0.f, 0.f);
        float4 vv = kv;
        if (kidx >= 0 && kidx < Lz) {
            kv = *(const float4*)(Kbase + (size_t)kidx * Dz + c);
            vv = *(const float4*)(Vbase + (size_t)kidx * Dz + c);
        }
        *(float4*)&Ks[r][c] = kv;
        *(float4*)&Vs[r][c] = vv;
    }
    __syncthreads();

    const int warp = tid >> 5;
    const int lane = tid & 31;
    const unsigned FULL = 0xffffffffu;

    for (int i = 0; i < 4; ++i) {
        const int l = q0 + warp * 4 + i;
        const int base = l - q0;
        const float qv0 = g_Q[bhbase + (size_t)l * Dz + lane];
        const float qv1 = g_Q[bhbase + (size_t)l * Dz + lane + 32];

        float s_lo = -INFINITY;
        float s_hi = -INFINITY;

#pragma unroll
        for (int w = 0; w < 33; ++w) {
            int row = base + w;
            float v = qv0 * Ks[row][lane] + qv1 * Ks[row][lane + 32];
            v += __shfl_xor_sync(FULL, v, 16);
            v += __shfl_xor_sync(FULL, v, 8);
            v += __shfl_xor_sync(FULL, v, 4);
            v += __shfl_xor_sync(FULL, v, 2);
            v += __shfl_xor_sync(FULL, v, 1);
            int kidx = l - PADz + w;
            float scv = (kidx >= 1 && kidx < Lz) ? v * SCALE : -INFINITY;
            if (w < 32) {
                if (lane == w) s_lo = scv;
            } else {
                if (lane == 0) s_hi = scv;
            }
        }
        {
            float v = qv0 * Ks[64][lane] + qv1 * Ks[64][lane + 32];
            v += __shfl_xor_sync(FULL, v, 16);
            v += __shfl_xor_sync(FULL, v, 8);
            v += __shfl_xor_sync(FULL, v, 4);
            v += __shfl_xor_sync(FULL, v, 2);
            v += __shfl_xor_sync(FULL, v, 1);
            if (lane == 1) s_hi = v * SCALE;
        }

        float m = fmaxf(s_lo, s_hi);
        m = fmaxf(m, __shfl_xor_sync(FULL, m, 16));
        m = fmaxf(m, __shfl_xor_sync(FULL, m, 8));
        m = fmaxf(m, __shfl_xor_sync(FULL, m, 4));
        m = fmaxf(m, __shfl_xor_sync(FULL, m, 2));
        m = fmaxf(m, __shfl_xor_sync(FULL, m, 1));

        float p_lo = __expf(s_lo - m);
        float p_hi = (lane < 2) ? __expf(s_hi - m) : 0.f;
        float t = p_lo + p_hi;
        t += __shfl_xor_sync(FULL, t, 16);
        t += __shfl_xor_sync(FULL, t, 8);
        t += __shfl_xor_sync(FULL, t, 4);
        t += __shfl_xor_sync(FULL, t, 2);
        t += __shfl_xor_sync(FULL, t, 1);
        const float inv = 1.f / t;

        float acc0 = 0.f, acc1 = 0.f;
#pragma unroll
        for (int w = 0; w < 32; ++w) {
            float p = __shfl_sync(FULL, p_lo, w);
            int row = base + w;
            acc0 = fmaf(p, Vs[row][lane],      acc0);
            acc1 = fmaf(p, Vs[row][lane + 32], acc1);
        }
        {
            float p32 = __shfl_sync(FULL, p_hi, 0);
            acc0 = fmaf(p32, Vs[base + 32][lane],      acc0);
            acc1 = fmaf(p32, Vs[base + 32][lane + 32], acc1);
            float pc = __shfl_sync(FULL, p_hi, 1);
            acc0 = fmaf(pc, Vs[64][lane],      acc0);
            acc1 = fmaf(pc, Vs[64][lane + 32], acc1);
        }

        float* op = g_attn + ((size_t)b * Lz + l) * Ez + h * Dz;
        op[lane]      = acc0 * inv;
        op[lane + 32] = acc1 * inv;
    }
}

// ---------------------------------------------------------------------------
// Launch
// ---------------------------------------------------------------------------
extern "C" void kernel_launch(void* const* d_in, const int* in_sizes, int n_in,
                              void* d_out, int out_size)
{
    const float* x  = (const float*)d_in[0];
    const float* Wq = (const float*)d_in[1];
    const float* bq = (const float*)d_in[2];
    const float* Wk = (const float*)d_in[3];
    const float* bk = (const float*)d_in[4];
    const float* Wv = (const float*)d_in[5];
    const float* bv = (const float*)d_in[6];
    const float* Wo = (const float*)d_in[7];
    const float* bo = (const float*)d_in[8];
    float* out = (float*)d_out;

    dim3 gridQKV(Ez / 128, (Mz + 127) / 128, 3);   // (3, 65, 3) = 585 CTAs
    dim3 gridO(Ez / 128, (Mz + 127) / 128);        // (3, 65)

    mma_gemm_kernel<1><<<gridQKV, 256>>>(x, Wq, bq, Wk, bk, Wv, bv, nullptr);

    cls_attn_kernel<<<dim3(Hz, Bz), 256>>>();
    win_attn_kernel<<<dim3(32, Hz, Bz), 256>>>();

    mma_gemm_kernel<0><<<gridO, 256>>>(nullptr, Wo, bo, nullptr, nullptr,
                                       nullptr, nullptr, out);
}

// round 5
// speedup vs baseline: 1.7158x; 1.1787x over previous
#include <cuda_runtime.h>
#include <cuda_bf16.h>
#include <math.h>
#include <cstdint>

// Problem constants
#define Bz   8
#define Lz   1025
#define Ez   384
#define Hz   6
#define Dz   64
#define PADz 16
#define Mz   (Bz * Lz)          // 8200 rows
#define SCALE 0.125f
#define WSZ  (Ez * Ez)          // 147456

// Scratch (device globals; no runtime allocation allowed)
__device__ float g_Q[Bz * Hz * Lz * Dz];
__device__ float g_K[Bz * Hz * Lz * Dz];
__device__ float g_V[Bz * Hz * Lz * Dz];
__device__ __nv_bfloat16 g_x_hi[Mz * Ez];
__device__ __nv_bfloat16 g_x_lo[Mz * Ez];
__device__ __nv_bfloat16 g_attn_hi[Mz * Ez];
__device__ __nv_bfloat16 g_attn_lo[Mz * Ez];
__device__ __nv_bfloat16 g_Wt_hi[4 * WSZ];   // transposed [z][n][k]
__device__ __nv_bfloat16 g_Wt_lo[4 * WSZ];

// ===========================================================================
// Helpers
// ===========================================================================
__device__ __forceinline__ uint32_t smem_u32(const void* p) {
    uint32_t a;
    asm("{ .reg .u64 t; cvta.to.shared.u64 t, %1; cvt.u32.u64 %0, t; }"
        : "=r"(a) : "l"(p));
    return a;
}

__device__ __forceinline__ void ldsm_x4(uint32_t (&r)[4], uint32_t saddr) {
    asm volatile("ldmatrix.sync.aligned.m8n8.x4.shared.b16 {%0,%1,%2,%3}, [%4];"
        : "=r"(r[0]), "=r"(r[1]), "=r"(r[2]), "=r"(r[3]) : "r"(saddr));
}

__device__ __forceinline__ void mma_bf16(float (&c)[4], const uint32_t (&a)[4],
                                         uint32_t b0, uint32_t b1) {
    asm volatile(
        "mma.sync.aligned.m16n8k16.row.col.f32.bf16.bf16.f32 "
        "{%0,%1,%2,%3}, {%4,%5,%6,%7}, {%8,%9}, {%0,%1,%2,%3};"
        : "+f"(c[0]), "+f"(c[1]), "+f"(c[2]), "+f"(c[3])
        : "r"(a[0]), "r"(a[1]), "r"(a[2]), "r"(a[3]), "r"(b0), "r"(b1));
}

__device__ __forceinline__ void cp_async16(uint32_t dst, const void* src, bool valid) {
    asm volatile("cp.async.ca.shared.global [%0], [%1], 16, %2;"
        :: "r"(dst), "l"(src), "r"(valid ? 16 : 0) : "memory");
}
#define CP_COMMIT() asm volatile("cp.async.commit_group;" ::: "memory")
template <int N>
__device__ __forceinline__ void cp_wait() {
    asm volatile("cp.async.wait_group %0;" :: "n"(N) : "memory");
}

__device__ __forceinline__ void split1(float x, __nv_bfloat16& h, __nv_bfloat16& l) {
    h = __float2bfloat16(x);
    l = __float2bfloat16(x - __bfloat162float(h));
}
__device__ __forceinline__ void split2(float x, float y, uint32_t& hi, uint32_t& lo) {
    __nv_bfloat16 hx, lx, hy, ly;
    split1(x, hx, lx);
    split1(y, hy, ly);
    hi = (uint32_t)__bfloat16_as_ushort(hx) | ((uint32_t)__bfloat16_as_ushort(hy) << 16);
    lo = (uint32_t)__bfloat16_as_ushort(lx) | ((uint32_t)__bfloat16_as_ushort(ly) << 16);
}

// ===========================================================================
// Prep kernels: fp32 -> bf16 hi/lo (x) and hi/lo transposed (weights)
// ===========================================================================
__global__ __launch_bounds__(256) void prep_x_kernel(const float* __restrict__ x)
{
    int idx4 = blockIdx.x * 256 + threadIdx.x;
    int base = idx4 * 4;
    if (base >= Mz * Ez) return;
    float4 v = *(const float4*)(x + base);
    uint32_t h01, l01, h23, l23;
    split2(v.x, v.y, h01, l01);
    split2(v.z, v.w, h23, l23);
    *(uint2*)((char*)g_x_hi + (size_t)base * 2) = make_uint2(h01, h23);
    *(uint2*)((char*)g_x_lo + (size_t)base * 2) = make_uint2(l01, l23);
}

__global__ __launch_bounds__(256) void prep_w_kernel(
    const float* __restrict__ Wq, const float* __restrict__ Wk,
    const float* __restrict__ Wv, const float* __restrict__ Wo)
{
    const int z = blockIdx.y;
    const float* W = (z == 0) ? Wq : (z == 1) ? Wk : (z == 2) ? Wv : Wo;
    int idx = blockIdx.x * 256 + threadIdx.x;    // over [n][k], k contiguous
    if (idx >= WSZ) return;
    int n = idx / Ez, k = idx - n * Ez;
    __nv_bfloat16 h, l;
    split1(W[(size_t)k * Ez + n], h, l);
    g_Wt_hi[(size_t)z * WSZ + idx] = h;
    g_Wt_lo[(size_t)z * WSZ + idx] = l;
}

// ===========================================================================
// HMMA GEMM with cp.async 2-stage pipeline.
// QKV=1: A = g_x (bf16 hi/lo), z=blockIdx.z in {0,1,2} -> g_Q/g_K/g_V scatter
// QKV=0: A = g_attn (bf16 hi/lo), z=3, write Cout row-major
// Tiles: CTA 128x128, K chunks of 32. 8 warps in 4(M) x 2(N).
// SMEM per stage: 4 arrays x 128 x 40 bf16 = 40960 B; 2 stages = 81920 B.
// ===========================================================================
#define KPAD  40
#define ARR_B 10240                 // bytes per array per stage
#define STG_B 40960                 // bytes per stage

template <int QKV>
__global__ __launch_bounds__(256) void mma_gemm_kernel(
    const float* __restrict__ b0, const float* __restrict__ b1,
    const float* __restrict__ b2, const float* __restrict__ b3,
    float* __restrict__ Cout)
{
    extern __shared__ __align__(16) char smem[];
    const uint32_t sb = smem_u32(smem);

    const int tid  = threadIdx.x;
    const int wid  = tid >> 5;
    const int lane = tid & 31;
    const int bn = blockIdx.x;
    const int bm = blockIdx.y;
    const int z  = QKV ? blockIdx.z : 3;

    const __nv_bfloat16* Ah = QKV ? g_x_hi : g_attn_hi;
    const __nv_bfloat16* Al = QKV ? g_x_lo : g_attn_lo;
    const __nv_bfloat16* Bh = g_Wt_hi + (size_t)z * WSZ;
    const __nv_bfloat16* Bl = g_Wt_lo + (size_t)z * WSZ;
    const float* bias = (z == 0) ? b0 : (z == 1) ? b1 : (z == 2) ? b2 : b3;

    const int m0 = bm * 128;
    const int n0 = bn * 128;
    const int wm = wid & 3;
    const int wn = wid >> 2;

    float acc[2][8][4];
#pragma unroll
    for (int mt = 0; mt < 2; ++mt)
#pragma unroll
        for (int nt = 0; nt < 8; ++nt)
#pragma unroll
            for (int q = 0; q < 4; ++q) acc[mt][nt][q] = 0.f;

    // staging thread mapping: 512 x 16B chunks per array, 2 per thread
    const int srow0 = tid >> 2;              // 0..63
    const int scol  = (tid & 3) * 8;         // bf16 element offset of 16B chunk

    // stage chunk c into stage buffer s
    auto stage = [&](int c, int s) {
        const uint32_t s0 = sb + s * STG_B;
#pragma unroll
        for (int t = 0; t < 2; ++t) {
            const int row = srow0 + t * 64;
            const uint32_t soff = (uint32_t)(row * KPAD + scol) * 2;
            const int ga = m0 + row;
            const size_t aidx = (size_t)ga * Ez + c * 32 + scol;
            const bool av = (ga < Mz);
            cp_async16(s0 + 0 * ARR_B + soff, Ah + aidx, av);
            cp_async16(s0 + 1 * ARR_B + soff, Al + aidx, av);
            const size_t bidx = (size_t)(n0 + row) * Ez + c * 32 + scol;
            cp_async16(s0 + 2 * ARR_B + soff, Bh + bidx, true);
            cp_async16(s0 + 3 * ARR_B + soff, Bl + bidx, true);
        }
    };

    const int grp = lane >> 3;
    const int wl  = lane & 7;

    stage(0, 0);
    CP_COMMIT();

    for (int c = 0; c < 12; ++c) {
        if (c < 11) {
            stage(c + 1, (c + 1) & 1);
            CP_COMMIT();
            cp_wait<1>();
        } else {
            cp_wait<0>();
        }
        __syncthreads();

        const uint32_t s0 = sb + (c & 1) * STG_B;
        const uint32_t sA_hi = s0;
        const uint32_t sA_lo = s0 + ARR_B;
        const uint32_t sB_hi = s0 + 2 * ARR_B;
        const uint32_t sB_lo = s0 + 3 * ARR_B;

#pragma unroll
        for (int ks = 0; ks < 2; ++ks) {
            const int k0 = ks * 16;
            uint32_t ah[2][4], al[2][4];
            const int a_r = wm * 32 + wl + (grp & 1) * 8;
            const int a_k = k0 + (grp >> 1) * 8;
#pragma unroll
            for (int mt = 0; mt < 2; ++mt) {
                uint32_t off = (uint32_t)((a_r + mt * 16) * KPAD + a_k) * 2;
                ldsm_x4(ah[mt], sA_hi + off);
                ldsm_x4(al[mt], sA_lo + off);
            }
            const int b_n = wn * 64 + wl + (grp >> 1) * 8;
            const int b_k = k0 + (grp & 1) * 8;
#pragma unroll
            for (int nt2 = 0; nt2 < 4; ++nt2) {
                uint32_t bh[4], bl[4];
                uint32_t off = (uint32_t)((b_n + nt2 * 16) * KPAD + b_k) * 2;
                ldsm_x4(bh, sB_hi + off);
                ldsm_x4(bl, sB_lo + off);
#pragma unroll
                for (int mt = 0; mt < 2; ++mt) {
                    mma_bf16(acc[mt][nt2 * 2 + 0], ah[mt], bh[0], bh[1]);
                    mma_bf16(acc[mt][nt2 * 2 + 0], ah[mt], bl[0], bl[1]);
                    mma_bf16(acc[mt][nt2 * 2 + 0], al[mt], bh[0], bh[1]);
                    mma_bf16(acc[mt][nt2 * 2 + 1], ah[mt], bh[2], bh[3]);
                    mma_bf16(acc[mt][nt2 * 2 + 1], ah[mt], bl[2], bl[3]);
                    mma_bf16(acc[mt][nt2 * 2 + 1], al[mt], bh[2], bh[3]);
                }
            }
        }
        __syncthreads();
    }

    // ---- epilogue ----
    const int tq = lane >> 2;
    const int tr = lane & 3;
#pragma unroll
    for (int mt = 0; mt < 2; ++mt) {
#pragma unroll
        for (int nt = 0; nt < 8; ++nt) {
            const int gcol = n0 + wn * 64 + nt * 8 + tr * 2;
            const float bv0 = bias[gcol];
            const float bv1 = bias[gcol + 1];
#pragma unroll
            for (int half = 0; half < 2; ++half) {
                const int grow = m0 + wm * 32 + mt * 16 + tq + half * 8;
                if (grow >= Mz) continue;
                float v0 = acc[mt][nt][half * 2 + 0] + bv0;
                float v1 = acc[mt][nt][half * 2 + 1] + bv1;
                if (QKV) {
                    int b = grow / Lz, l = grow - b * Lz;
                    int h = gcol >> 6, d = gcol & 63;
                    float* dst = (z == 0) ? g_Q : (z == 1) ? g_K : g_V;
                    *(float2*)(dst + (((size_t)(b * Hz + h)) * Lz + l) * Dz + d) =
                        make_float2(v0, v1);
                } else {
                    *(float2*)(Cout + (size_t)grow * Ez + gcol) = make_float2(v0, v1);
                }
            }
        }
    }
}

// ---------------------------------------------------------------------------
// CLS attention: query l=0 attends to all L keys. One block per (h, b).
// Writes bf16 hi/lo attention output.
// ---------------------------------------------------------------------------
__global__ __launch_bounds__(256) void cls_attn_kernel()
{
    const int h = blockIdx.x;
    const int b = blockIdx.y;
    const int tid = threadIdx.x;

    __shared__ float qv[Dz];
    __shared__ float sc[Lz];
    __shared__ float red[256];

    const size_t base = ((size_t)(b * Hz + h)) * Lz * Dz;
    const float* Qp = g_Q + base;
    const float* Kp = g_K + base;
    const float* Vp = g_V + base;

    if (tid < Dz) qv[tid] = Qp[tid];
    __syncthreads();

    float lmax = -INFINITY;
    for (int k = tid; k < Lz; k += 256) {
        const float* kr = Kp + (size_t)k * Dz;
        float s = 0.f;
#pragma unroll 16
        for (int d = 0; d < Dz; ++d) s = fmaf(qv[d], kr[d], s);
        s *= SCALE;
        sc[k] = s;
        lmax = fmaxf(lmax, s);
    }
    red[tid] = lmax;
    __syncthreads();
    for (int s2 = 128; s2 > 0; s2 >>= 1) {
        if (tid < s2) red[tid] = fmaxf(red[tid], red[tid + s2]);
        __syncthreads();
    }
    const float m = red[0];
    __syncthreads();

    float lsum = 0.f;
    for (int k = tid; k < Lz; k += 256) {
        float p = __expf(sc[k] - m);
        sc[k] = p;
        lsum += p;
    }
    red[tid] = lsum;
    __syncthreads();
    for (int s2 = 128; s2 > 0; s2 >>= 1) {
        if (tid < s2) red[tid] += red[tid + s2];
        __syncthreads();
    }
    const float inv = 1.f / red[0];

    if (tid < Dz) {
        float a0 = 0.f, a1 = 0.f, a2 = 0.f, a3 = 0.f;
        int k = 0;
        for (; k + 3 < Lz; k += 4) {
            a0 = fmaf(sc[k + 0], Vp[(size_t)(k + 0) * Dz + tid], a0);
            a1 = fmaf(sc[k + 1], Vp[(size_t)(k + 1) * Dz + tid], a1);
            a2 = fmaf(sc[k + 2], Vp[(size_t)(k + 2) * Dz + tid], a2);
            a3 = fmaf(sc[k + 3], Vp[(size_t)(k + 3) * Dz + tid], a3);
        }
        for (; k < Lz; ++k) a0 = fmaf(sc[k], Vp[(size_t)k * Dz + tid], a0);
        float acc = ((a0 + a1) + (a2 + a3)) * inv;
        __nv_bfloat16 hh, ll;
        split1(acc, hh, ll);
        size_t o = ((size_t)b * Lz) * Ez + h * Dz + tid;
        g_attn_hi[o] = hh;
        g_attn_lo[o] = ll;
    }
}

// ---------------------------------------------------------------------------
// Windowed attention for queries l=1..L-1, bf16 hi/lo output.
// ---------------------------------------------------------------------------
__global__ __launch_bounds__(256) void win_attn_kernel()
{
    const int bx = blockIdx.x;
    const int h  = blockIdx.y;
    const int b  = blockIdx.z;
    const int tid = threadIdx.x;

    __shared__ float Ks[65][64];
    __shared__ float Vs[65][64];

    const int q0 = 1 + bx * 32;
    const size_t bhbase = ((size_t)(b * Hz + h)) * Lz * Dz;
    const float* Kbase = g_K + bhbase;
    const float* Vbase = g_V + bhbase;

    for (int i = tid; i < 65 * 16; i += 256) {
        int r = i >> 4;
        int c = (i & 15) * 4;
        int kidx = (r == 64) ? 0 : (q0 - 16 + r);
        float4 kv = make_float4(0.f, 0.f, 0.f, 0.f);
        float4 vv = kv;
        if (kidx >= 0 && kidx < Lz) {
            kv = *(const float4*)(Kbase + (size_t)kidx * Dz + c);
            vv = *(const float4*)(Vbase + (size_t)kidx * Dz + c);
        }
        *(float4*)&Ks[r][c] = kv;
        *(float4*)&Vs[r][c] = vv;
    }
    __syncthreads();

    const int warp = tid >> 5;
    const int lane = tid & 31;
    const unsigned FULL = 0xffffffffu;

    for (int i = 0; i < 4; ++i) {
        const int l = q0 + warp * 4 + i;
        const int base = l - q0;
        const float qv0 = g_Q[bhbase + (size_t)l * Dz + lane];
        const float qv1 = g_Q[bhbase + (size_t)l * Dz + lane + 32];

        float s_lo = -INFINITY;
        float s_hi = -INFINITY;

#pragma unroll
        for (int w = 0; w < 33; ++w) {
            int row = base + w;
            float v = qv0 * Ks[row][lane] + qv1 * Ks[row][lane + 32];
            v += __shfl_xor_sync(FULL, v, 16);
            v += __shfl_xor_sync(FULL, v, 8);
            v += __shfl_xor_sync(FULL, v, 4);
            v += __shfl_xor_sync(FULL, v, 2);
            v += __shfl_xor_sync(FULL, v, 1);
            int kidx = l - PADz + w;
            float scv = (kidx >= 1 && kidx < Lz) ? v * SCALE : -INFINITY;
            if (w < 32) {
                if (lane == w) s_lo = scv;
            } else {
                if (lane == 0) s_hi = scv;
            }
        }
        {
            float v = qv0 * Ks[64][lane] + qv1 * Ks[64][lane + 32];
            v += __shfl_xor_sync(FULL, v, 16);
            v += __shfl_xor_sync(FULL, v, 8);
            v += __shfl_xor_sync(FULL, v, 4);
            v += __shfl_xor_sync(FULL, v, 2);
            v += __shfl_xor_sync(FULL, v, 1);
            if (lane == 1) s_hi = v * SCALE;
        }

        float m = fmaxf(s_lo, s_hi);
        m = fmaxf(m, __shfl_xor_sync(FULL, m, 16));
        m = fmaxf(m, __shfl_xor_sync(FULL, m, 8));
        m = fmaxf(m, __shfl_xor_sync(FULL, m, 4));
        m = fmaxf(m, __shfl_xor_sync(FULL, m, 2));
        m = fmaxf(m, __shfl_xor_sync(FULL, m, 1));

        float p_lo = __expf(s_lo - m);
        float p_hi = (lane < 2) ? __expf(s_hi - m) : 0.f;
        float t = p_lo + p_hi;
        t += __shfl_xor_sync(FULL, t, 16);
        t += __shfl_xor_sync(FULL, t, 8);
        t += __shfl_xor_sync(FULL, t, 4);
        t += __shfl_xor_sync(FULL, t, 2);
        t += __shfl_xor_sync(FULL, t, 1);
        const float inv = 1.f / t;

        float acc0 = 0.f, acc1 = 0.f;
#pragma unroll
        for (int w = 0; w < 32; ++w) {
            float p = __shfl_sync(FULL, p_lo, w);
            int row = base + w;
            acc0 = fmaf(p, Vs[row][lane],      acc0);
            acc1 = fmaf(p, Vs[row][lane + 32], acc1);
        }
        {
            float p32 = __shfl_sync(FULL, p_hi, 0);
            acc0 = fmaf(p32, Vs[base + 32][lane],      acc0);
            acc1 = fmaf(p32, Vs[base + 32][lane + 32], acc1);
            float pc = __shfl_sync(FULL, p_hi, 1);
            acc0 = fmaf(pc, Vs[64][lane],      acc0);
            acc1 = fmaf(pc, Vs[64][lane + 32], acc1);
        }

        acc0 *= inv;
        acc1 *= inv;
        __nv_bfloat16 h0, l0, h1, l1;
        split1(acc0, h0, l0);
        split1(acc1, h1, l1);
        size_t o = ((size_t)b * Lz + l) * Ez + h * Dz;
        g_attn_hi[o + lane]      = h0;
        g_attn_lo[o + lane]      = l0;
        g_attn_hi[o + lane + 32] = h1;
        g_attn_lo[o + lane + 32] = l1;
    }
}

// ---------------------------------------------------------------------------
// Launch
// ---------------------------------------------------------------------------
extern "C" void kernel_launch(void* const* d_in, const int* in_sizes, int n_in,
                              void* d_out, int out_size)
{
    const float* x  = (const float*)d_in[0];
    const float* Wq = (const float*)d_in[1];
    const float* bq = (const float*)d_in[2];
    const float* Wk = (const float*)d_in[3];
    const float* bk = (const float*)d_in[4];
    const float* Wv = (const float*)d_in[5];
    const float* bv = (const float*)d_in[6];
    const float* Wo = (const float*)d_in[7];
    const float* bo = (const float*)d_in[8];
    float* out = (float*)d_out;

    static bool attr_done = false;
    if (!attr_done) {
        cudaFuncSetAttribute((const void*)mma_gemm_kernel<1>,
                             cudaFuncAttributeMaxDynamicSharedMemorySize, 2 * STG_B);
        cudaFuncSetAttribute((const void*)mma_gemm_kernel<0>,
                             cudaFuncAttributeMaxDynamicSharedMemorySize, 2 * STG_B);
        attr_done = true;
    }

    // prep: bf16 hi/lo conversions
    prep_x_kernel<<<(Mz * Ez / 4 + 255) / 256, 256>>>(x);
    prep_w_kernel<<<dim3((WSZ + 255) / 256, 4), 256>>>(Wq, Wk, Wv, Wo);

    dim3 gridQKV(Ez / 128, (Mz + 127) / 128, 3);   // 585 CTAs
    dim3 gridO(Ez / 128, (Mz + 127) / 128);        // 195 CTAs

    mma_gemm_kernel<1><<<gridQKV, 256, 2 * STG_B>>>(bq, bk, bv, bo, nullptr);

    cls_attn_kernel<<<dim3(Hz, Bz), 256>>>();
    win_attn_kernel<<<dim3(32, Hz, Bz), 256>>>();

    mma_gemm_kernel<0><<<gridO, 256, 2 * STG_B>>>(bq, bk, bv, bo, out);
}

// round 6
// speedup vs baseline: 2.3180x; 1.3510x over previous
#include <cuda_runtime.h>
#include <cuda_bf16.h>
#include <math.h>
#include <cstdint>

// Problem constants
#define Bz   8
#define Lz   1025
#define Ez   384
#define Hz   6
#define Dz   64
#define PADz 16
#define Mz   (Bz * Lz)          // 8200 rows
#define SCALE 0.125f
#define WSZ  (Ez * Ez)          // 147456

// CLS split-K attention
#define CSPL  16
#define CKEYS 65                // ceil(1025/16)

// Scratch (device globals; no runtime allocation allowed)
__device__ float g_Q[Bz * Hz * Lz * Dz];
__device__ float g_K[Bz * Hz * Lz * Dz];
__device__ float g_V[Bz * Hz * Lz * Dz];
__device__ __nv_bfloat16 g_x_hi[Mz * Ez];
__device__ __nv_bfloat16 g_x_lo[Mz * Ez];
__device__ __nv_bfloat16 g_attn_hi[Mz * Ez];
__device__ __nv_bfloat16 g_attn_lo[Mz * Ez];
__device__ __nv_bfloat16 g_Wt_hi[4 * WSZ];   // transposed [z][n][k]
__device__ __nv_bfloat16 g_Wt_lo[4 * WSZ];
__device__ float g_cls_m[Bz * Hz * CSPL];
__device__ float g_cls_s[Bz * Hz * CSPL];
__device__ float g_cls_o[Bz * Hz * CSPL * Dz];

// ===========================================================================
// Helpers
// ===========================================================================
__device__ __forceinline__ uint32_t smem_u32(const void* p) {
    uint32_t a;
    asm("{ .reg .u64 t; cvta.to.shared.u64 t, %1; cvt.u32.u64 %0, t; }"
        : "=r"(a) : "l"(p));
    return a;
}

__device__ __forceinline__ void ldsm_x4(uint32_t (&r)[4], uint32_t saddr) {
    asm volatile("ldmatrix.sync.aligned.m8n8.x4.shared.b16 {%0,%1,%2,%3}, [%4];"
        : "=r"(r[0]), "=r"(r[1]), "=r"(r[2]), "=r"(r[3]) : "r"(saddr));
}

__device__ __forceinline__ void mma_bf16(float (&c)[4], const uint32_t (&a)[4],
                                         uint32_t b0, uint32_t b1) {
    asm volatile(
        "mma.sync.aligned.m16n8k16.row.col.f32.bf16.bf16.f32 "
        "{%0,%1,%2,%3}, {%4,%5,%6,%7}, {%8,%9}, {%0,%1,%2,%3};"
        : "+f"(c[0]), "+f"(c[1]), "+f"(c[2]), "+f"(c[3])
        : "r"(a[0]), "r"(a[1]), "r"(a[2]), "r"(a[3]), "r"(b0), "r"(b1));
}

__device__ __forceinline__ void cp_async16(uint32_t dst, const void* src, bool valid) {
    asm volatile("cp.async.ca.shared.global [%0], [%1], 16, %2;"
        :: "r"(dst), "l"(src), "r"(valid ? 16 : 0) : "memory");
}
#define CP_COMMIT() asm volatile("cp.async.commit_group;" ::: "memory")
template <int N>
__device__ __forceinline__ void cp_wait() {
    asm volatile("cp.async.wait_group %0;" :: "n"(N) : "memory");
}

__device__ __forceinline__ void split1(float x, __nv_bfloat16& h, __nv_bfloat16& l) {
    h = __float2bfloat16(x);
    l = __float2bfloat16(x - __bfloat162float(h));
}
__device__ __forceinline__ void split2(float x, float y, uint32_t& hi, uint32_t& lo) {
    __nv_bfloat16 hx, lx, hy, ly;
    split1(x, hx, lx);
    split1(y, hy, ly);
    hi = (uint32_t)__bfloat16_as_ushort(hx) | ((uint32_t)__bfloat16_as_ushort(hy) << 16);
    lo = (uint32_t)__bfloat16_as_ushort(lx) | ((uint32_t)__bfloat16_as_ushort(ly) << 16);
}

// ===========================================================================
// Prep kernels: fp32 -> bf16 hi/lo (x) and hi/lo transposed (weights)
// ===========================================================================
__global__ __launch_bounds__(256) void prep_x_kernel(const float* __restrict__ x)
{
    int idx4 = blockIdx.x * 256 + threadIdx.x;
    int base = idx4 * 4;
    if (base >= Mz * Ez) return;
    float4 v = *(const float4*)(x + base);
    uint32_t h01, l01, h23, l23;
    split2(v.x, v.y, h01, l01);
    split2(v.z, v.w, h23, l23);
    *(uint2*)((char*)g_x_hi + (size_t)base * 2) = make_uint2(h01, h23);
    *(uint2*)((char*)g_x_lo + (size_t)base * 2) = make_uint2(l01, l23);
}

__global__ __launch_bounds__(256) void prep_w_kernel(
    const float* __restrict__ Wq, const float* __restrict__ Wk,
    const float* __restrict__ Wv, const float* __restrict__ Wo)
{
    const int z = blockIdx.y;
    const float* W = (z == 0) ? Wq : (z == 1) ? Wk : (z == 2) ? Wv : Wo;
    int idx = blockIdx.x * 256 + threadIdx.x;    // over [n][k], k contiguous
    if (idx >= WSZ) return;
    int n = idx / Ez, k = idx - n * Ez;
    __nv_bfloat16 h, l;
    split1(W[(size_t)k * Ez + n], h, l);
    g_Wt_hi[(size_t)z * WSZ + idx] = h;
    g_Wt_lo[(size_t)z * WSZ + idx] = l;
}

// ===========================================================================
// HMMA GEMM with cp.async 2-stage pipeline (unchanged from R5).
// ===========================================================================
#define KPAD  40
#define ARR_B 10240
#define STG_B 40960

template <int QKV>
__global__ __launch_bounds__(256) void mma_gemm_kernel(
    const float* __restrict__ b0, const float* __restrict__ b1,
    const float* __restrict__ b2, const float* __restrict__ b3,
    float* __restrict__ Cout)
{
    extern __shared__ __align__(16) char smem[];
    const uint32_t sb = smem_u32(smem);

    const int tid  = threadIdx.x;
    const int wid  = tid >> 5;
    const int lane = tid & 31;
    const int bn = blockIdx.x;
    const int bm = blockIdx.y;
    const int z  = QKV ? blockIdx.z : 3;

    const __nv_bfloat16* Ah = QKV ? g_x_hi : g_attn_hi;
    const __nv_bfloat16* Al = QKV ? g_x_lo : g_attn_lo;
    const __nv_bfloat16* Bh = g_Wt_hi + (size_t)z * WSZ;
    const __nv_bfloat16* Bl = g_Wt_lo + (size_t)z * WSZ;
    const float* bias = (z == 0) ? b0 : (z == 1) ? b1 : (z == 2) ? b2 : b3;

    const int m0 = bm * 128;
    const int n0 = bn * 128;
    const int wm = wid & 3;
    const int wn = wid >> 2;

    float acc[2][8][4];
#pragma unroll
    for (int mt = 0; mt < 2; ++mt)
#pragma unroll
        for (int nt = 0; nt < 8; ++nt)
#pragma unroll
            for (int q = 0; q < 4; ++q) acc[mt][nt][q] = 0.f;

    const int srow0 = tid >> 2;
    const int scol  = (tid & 3) * 8;

    auto stage = [&](int c, int s) {
        const uint32_t s0 = sb + s * STG_B;
#pragma unroll
        for (int t = 0; t < 2; ++t) {
            const int row = srow0 + t * 64;
            const uint32_t soff = (uint32_t)(row * KPAD + scol) * 2;
            const int ga = m0 + row;
            const size_t aidx = (size_t)ga * Ez + c * 32 + scol;
            const bool av = (ga < Mz);
            cp_async16(s0 + 0 * ARR_B + soff, Ah + aidx, av);
            cp_async16(s0 + 1 * ARR_B + soff, Al + aidx, av);
            const size_t bidx = (size_t)(n0 + row) * Ez + c * 32 + scol;
            cp_async16(s0 + 2 * ARR_B + soff, Bh + bidx, true);
            cp_async16(s0 + 3 * ARR_B + soff, Bl + bidx, true);
        }
    };

    const int grp = lane >> 3;
    const int wl  = lane & 7;

    stage(0, 0);
    CP_COMMIT();

    for (int c = 0; c < 12; ++c) {
        if (c < 11) {
            stage(c + 1, (c + 1) & 1);
            CP_COMMIT();
            cp_wait<1>();
        } else {
            cp_wait<0>();
        }
        __syncthreads();

        const uint32_t s0 = sb + (c & 1) * STG_B;
        const uint32_t sA_hi = s0;
        const uint32_t sA_lo = s0 + ARR_B;
        const uint32_t sB_hi = s0 + 2 * ARR_B;
        const uint32_t sB_lo = s0 + 3 * ARR_B;

#pragma unroll
        for (int ks = 0; ks < 2; ++ks) {
            const int k0 = ks * 16;
            uint32_t ah[2][4], al[2][4];
            const int a_r = wm * 32 + wl + (grp & 1) * 8;
            const int a_k = k0 + (grp >> 1) * 8;
#pragma unroll
            for (int mt = 0; mt < 2; ++mt) {
                uint32_t off = (uint32_t)((a_r + mt * 16) * KPAD + a_k) * 2;
                ldsm_x4(ah[mt], sA_hi + off);
                ldsm_x4(al[mt], sA_lo + off);
            }
            const int b_n = wn * 64 + wl + (grp >> 1) * 8;
            const int b_k = k0 + (grp & 1) * 8;
#pragma unroll
            for (int nt2 = 0; nt2 < 4; ++nt2) {
                uint32_t bh[4], bl[4];
                uint32_t off = (uint32_t)((b_n + nt2 * 16) * KPAD + b_k) * 2;
                ldsm_x4(bh, sB_hi + off);
                ldsm_x4(bl, sB_lo + off);
#pragma unroll
                for (int mt = 0; mt < 2; ++mt) {
                    mma_bf16(acc[mt][nt2 * 2 + 0], ah[mt], bh[0], bh[1]);
                    mma_bf16(acc[mt][nt2 * 2 + 0], ah[mt], bl[0], bl[1]);
                    mma_bf16(acc[mt][nt2 * 2 + 0], al[mt], bh[0], bh[1]);
                    mma_bf16(acc[mt][nt2 * 2 + 1], ah[mt], bh[2], bh[3]);
                    mma_bf16(acc[mt][nt2 * 2 + 1], ah[mt], bl[2], bl[3]);
                    mma_bf16(acc[mt][nt2 * 2 + 1], al[mt], bh[2], bh[3]);
                }
            }
        }
        __syncthreads();
    }

    const int tq = lane >> 2;
    const int tr = lane & 3;
#pragma unroll
    for (int mt = 0; mt < 2; ++mt) {
#pragma unroll
        for (int nt = 0; nt < 8; ++nt) {
            const int gcol = n0 + wn * 64 + nt * 8 + tr * 2;
            const float bv0 = bias[gcol];
            const float bv1 = bias[gcol + 1];
#pragma unroll
            for (int half = 0; half < 2; ++half) {
                const int grow = m0 + wm * 32 + mt * 16 + tq + half * 8;
                if (grow >= Mz) continue;
                float v0 = acc[mt][nt][half * 2 + 0] + bv0;
                float v1 = acc[mt][nt][half * 2 + 1] + bv1;
                if (QKV) {
                    int b = grow / Lz, l = grow - b * Lz;
                    int h = gcol >> 6, d = gcol & 63;
                    float* dst = (z == 0) ? g_Q : (z == 1) ? g_K : g_V;
                    *(float2*)(dst + (((size_t)(b * Hz + h)) * Lz + l) * Dz + d) =
                        make_float2(v0, v1);
                } else {
                    *(float2*)(Cout + (size_t)grow * Ez + gcol) = make_float2(v0, v1);
                }
            }
        }
    }
}

// ---------------------------------------------------------------------------
// CLS attention, split-K partials: grid (CSPL, Hz, Bz), 128 threads.
// Each block: ~65 keys -> local softmax (m, S) + weighted-V partial.
// ---------------------------------------------------------------------------
__global__ __launch_bounds__(128) void cls_part_kernel()
{
    const int sp = blockIdx.x;
    const int h  = blockIdx.y;
    const int b  = blockIdx.z;
    const int tid = threadIdx.x;
    const int warp = tid >> 5;
    const int lane = tid & 31;
    const unsigned FULL = 0xffffffffu;

    __shared__ float qv[Dz];
    __shared__ float sc[CKEYS];
    __shared__ float redm[4];
    __shared__ float reds[4];
    __shared__ float oacc[2][Dz];

    const size_t base = ((size_t)(b * Hz + h)) * Lz * Dz;
    const int k0 = sp * CKEYS;
    const int nk = min(CKEYS, Lz - k0);

    if (tid < Dz) qv[tid] = g_Q[base + tid];
    __syncthreads();

    // scores: one warp per key, strided by 4 warps
    float lmax = -INFINITY;
    for (int i = warp; i < nk; i += 4) {
        const float* kr = g_K + base + (size_t)(k0 + i) * Dz;
        float v = qv[lane] * kr[lane] + qv[lane + 32] * kr[lane + 32];
        v += __shfl_xor_sync(FULL, v, 16);
        v += __shfl_xor_sync(FULL, v, 8);
        v += __shfl_xor_sync(FULL, v, 4);
        v += __shfl_xor_sync(FULL, v, 2);
        v += __shfl_xor_sync(FULL, v, 1);
        v *= SCALE;
        if (lane == 0) sc[i] = v;
        lmax = fmaxf(lmax, v);
    }
    if (lane == 0) redm[warp] = lmax;
    __syncthreads();
    const float m = fmaxf(fmaxf(redm[0], redm[1]), fmaxf(redm[2], redm[3]));

    // exp + local sum
    float ls = 0.f;
    for (int i = tid; i < nk; i += 128) {
        float p = __expf(sc[i] - m);
        sc[i] = p;
        ls += p;
    }
    ls += __shfl_xor_sync(FULL, ls, 16);
    ls += __shfl_xor_sync(FULL, ls, 8);
    ls += __shfl_xor_sync(FULL, ls, 4);
    ls += __shfl_xor_sync(FULL, ls, 2);
    ls += __shfl_xor_sync(FULL, ls, 1);
    if (lane == 0) reds[warp] = ls;
    __syncthreads();
    const float S = reds[0] + reds[1] + reds[2] + reds[3];

    // weighted V partial: 2 groups x 64 dims
    const int g = tid >> 6;      // 0..1
    const int d = tid & 63;
    float a = 0.f;
    for (int i = g; i < nk; i += 2)
        a = fmaf(sc[i], g_V[base + (size_t)(k0 + i) * Dz + d], a);
    oacc[g][d] = a;
    __syncthreads();

    if (tid < Dz) {
        const int idx = (b * Hz + h) * CSPL + sp;
        g_cls_o[(size_t)idx * Dz + tid] = oacc[0][tid] + oacc[1][tid];
        if (tid == 0) { g_cls_m[idx] = m; g_cls_s[idx] = S; }
    }
}

// ---------------------------------------------------------------------------
// CLS combine: grid (Hz, Bz), 64 threads. Merge CSPL partials, emit bf16.
// ---------------------------------------------------------------------------
__global__ __launch_bounds__(64) void cls_comb_kernel()
{
    const int h = blockIdx.x;
    const int b = blockIdx.y;
    const int d = threadIdx.x;
    const int base = (b * Hz + h) * CSPL;

    float M = -INFINITY;
#pragma unroll
    for (int j = 0; j < CSPL; ++j) M = fmaxf(M, g_cls_m[base + j]);
    float S = 0.f, o = 0.f;
#pragma unroll
    for (int j = 0; j < CSPL; ++j) {
        float w = __expf(g_cls_m[base + j] - M);
        S = fmaf(g_cls_s[base + j], w, S);
        o = fmaf(g_cls_o[(size_t)(base + j) * Dz + d], w, o);
    }
    float acc = o / S;
    __nv_bfloat16 hh, ll;
    split1(acc, hh, ll);
    size_t off = ((size_t)b * Lz) * Ez + h * Dz + d;
    g_attn_hi[off] = hh;
    g_attn_lo[off] = ll;
}

// ---------------------------------------------------------------------------
// Windowed attention for queries l=1..L-1, bf16 hi/lo output (unchanged).
// ---------------------------------------------------------------------------
__global__ __launch_bounds__(256) void win_attn_kernel()
{
    const int bx = blockIdx.x;
    const int h  = blockIdx.y;
    const int b  = blockIdx.z;
    const int tid = threadIdx.x;

    __shared__ float Ks[65][64];
    __shared__ float Vs[65][64];

    const int q0 = 1 + bx * 32;
    const size_t bhbase = ((size_t)(b * Hz + h)) * Lz * Dz;
    const float* Kbase = g_K + bhbase;
    const float* Vbase = g_V + bhbase;

    for (int i = tid; i < 65 * 16; i += 256) {
        int r = i >> 4;
        int c = (i & 15) * 4;
        int kidx = (r == 64) ? 0 : (q0 - 16 + r);
        float4 kv = make_float4(0.f, 0.f, 0.f, 0.f);
        float4 vv = kv;
        if (kidx >= 0 && kidx < Lz) {
            kv = *(const float4*)(Kbase + (size_t)kidx * Dz + c);
            vv = *(const float4*)(Vbase + (size_t)kidx * Dz + c);
        }
        *(float4*)&Ks[r][c] = kv;
        *(float4*)&Vs[r][c] = vv;
    }
    __syncthreads();

    const int warp = tid >> 5;
    const int lane = tid & 31;
    const unsigned FULL = 0xffffffffu;

    for (int i = 0; i < 4; ++i) {
        const int l = q0 + warp * 4 + i;
        const int base = l - q0;
        const float qv0 = g_Q[bhbase + (size_t)l * Dz + lane];
        const float qv1 = g_Q[bhbase + (size_t)l * Dz + lane + 32];

        float s_lo = -INFINITY;
        float s_hi = -INFINITY;

#pragma unroll
        for (int w = 0; w < 33; ++w) {
            int row = base + w;
            float v = qv0 * Ks[row][lane] + qv1 * Ks[row][lane + 32];
            v += __shfl_xor_sync(FULL, v, 16);
            v += __shfl_xor_sync(FULL, v, 8);
            v += __shfl_xor_sync(FULL, v, 4);
            v += __shfl_xor_sync(FULL, v, 2);
            v += __shfl_xor_sync(FULL, v, 1);
            int kidx = l - PADz + w;
            float scv = (kidx >= 1 && kidx < Lz) ? v * SCALE : -INFINITY;
            if (w < 32) {
                if (lane == w) s_lo = scv;
            } else {
                if (lane == 0) s_hi = scv;
            }
        }
        {
            float v = qv0 * Ks[64][lane] + qv1 * Ks[64][lane + 32];
            v += __shfl_xor_sync(FULL, v, 16);
            v += __shfl_xor_sync(FULL, v, 8);
            v += __shfl_xor_sync(FULL, v, 4);
            v += __shfl_xor_sync(FULL, v, 2);
            v += __shfl_xor_sync(FULL, v, 1);
            if (lane == 1) s_hi = v * SCALE;
        }

        float m = fmaxf(s_lo, s_hi);
        m = fmaxf(m, __shfl_xor_sync(FULL, m, 16));
        m = fmaxf(m, __shfl_xor_sync(FULL, m, 8));
        m = fmaxf(m, __shfl_xor_sync(FULL, m, 4));
        m = fmaxf(m, __shfl_xor_sync(FULL, m, 2));
        m = fmaxf(m, __shfl_xor_sync(FULL, m, 1));

        float p_lo = __expf(s_lo - m);
        float p_hi = (lane < 2) ? __expf(s_hi - m) : 0.f;
        float t = p_lo + p_hi;
        t += __shfl_xor_sync(FULL, t, 16);
        t += __shfl_xor_sync(FULL, t, 8);
        t += __shfl_xor_sync(FULL, t, 4);
        t += __shfl_xor_sync(FULL, t, 2);
        t += __shfl_xor_sync(FULL, t, 1);
        const float inv = 1.f / t;

        float acc0 = 0.f, acc1 = 0.f;
#pragma unroll
        for (int w = 0; w < 32; ++w) {
            float p = __shfl_sync(FULL, p_lo, w);
            int row = base + w;
            acc0 = fmaf(p, Vs[row][lane],      acc0);
            acc1 = fmaf(p, Vs[row][lane + 32], acc1);
        }
        {
            float p32 = __shfl_sync(FULL, p_hi, 0);
            acc0 = fmaf(p32, Vs[base + 32][lane],      acc0);
            acc1 = fmaf(p32, Vs[base + 32][lane + 32], acc1);
            float pc = __shfl_sync(FULL, p_hi, 1);
            acc0 = fmaf(pc, Vs[64][lane],      acc0);
            acc1 = fmaf(pc, Vs[64][lane + 32], acc1);
        }

        acc0 *= inv;
        acc1 *= inv;
        __nv_bfloat16 h0, l0, h1, l1;
        split1(acc0, h0, l0);
        split1(acc1, h1, l1);
        size_t o = ((size_t)b * Lz + l) * Ez + h * Dz;
        g_attn_hi[o + lane]      = h0;
        g_attn_lo[o + lane]      = l0;
        g_attn_hi[o + lane + 32] = h1;
        g_attn_lo[o + lane + 32] = l1;
    }
}

// ---------------------------------------------------------------------------
// Launch
// ---------------------------------------------------------------------------
extern "C" void kernel_launch(void* const* d_in, const int* in_sizes, int n_in,
                              void* d_out, int out_size)
{
    const float* x  = (const float*)d_in[0];
    const float* Wq = (const float*)d_in[1];
    const float* bq = (const float*)d_in[2];
    const float* Wk = (const float*)d_in[3];
    const float* bk = (const float*)d_in[4];
    const float* Wv = (const float*)d_in[5];
    const float* bv = (const float*)d_in[6];
    const float* Wo = (const float*)d_in[7];
    const float* bo = (const float*)d_in[8];
    float* out = (float*)d_out;

    static bool attr_done = false;
    if (!attr_done) {
        cudaFuncSetAttribute((const void*)mma_gemm_kernel<1>,
                             cudaFuncAttributeMaxDynamicSharedMemorySize, 2 * STG_B);
        cudaFuncSetAttribute((const void*)mma_gemm_kernel<0>,
                             cudaFuncAttributeMaxDynamicSharedMemorySize, 2 * STG_B);
        attr_done = true;
    }

    prep_x_kernel<<<(Mz * Ez / 4 + 255) / 256, 256>>>(x);
    prep_w_kernel<<<dim3((WSZ + 255) / 256, 4), 256>>>(Wq, Wk, Wv, Wo);

    dim3 gridQKV(Ez / 128, (Mz + 127) / 128, 3);   // 585 CTAs
    dim3 gridO(Ez / 128, (Mz + 127) / 128);        // 195 CTAs

    mma_gemm_kernel<1><<<gridQKV, 256, 2 * STG_B>>>(bq, bk, bv, bo, nullptr);

    cls_part_kernel<<<dim3(CSPL, Hz, Bz), 128>>>();
    cls_comb_kernel<<<dim3(Hz, Bz), 64>>>();
    win_attn_kernel<<<dim3(32, Hz, Bz), 256>>>();

    mma_gemm_kernel<0><<<gridO, 256, 2 * STG_B>>>(bq, bk, bv, bo, out);
}

// round 7
// speedup vs baseline: 2.5246x; 1.0891x over previous
#include <cuda_runtime.h>
#include <cuda_bf16.h>
#include <math.h>
#include <cstdint>

// Problem constants
#define Bz   8
#define Lz   1025
#define Ez   384
#define Hz   6
#define Dz   64
#define PADz 16
#define Mz   (Bz * Lz)          // 8200 rows
#define SCALE 0.125f
#define WSZ  (Ez * Ez)          // 147456

// CLS split-K attention
#define CSPL  16
#define CKEYS 65                // ceil(1025/16)

// Scratch (device globals; no runtime allocation allowed)
__device__ float g_Q[Bz * Hz * Lz * Dz];
__device__ float g_K[Bz * Hz * Lz * Dz];
__device__ float g_V[Bz * Hz * Lz * Dz];
__device__ __nv_bfloat16 g_x_hi[Mz * Ez];
__device__ __nv_bfloat16 g_x_lo[Mz * Ez];
__device__ __nv_bfloat16 g_attn_hi[Mz * Ez];
__device__ __nv_bfloat16 g_attn_lo[Mz * Ez];
__device__ __nv_bfloat16 g_Wt_hi[4 * WSZ];   // transposed [z][n][k]
__device__ __nv_bfloat16 g_Wt_lo[4 * WSZ];
__device__ float g_cls_m[Bz * Hz * CSPL];
__device__ float g_cls_s[Bz * Hz * CSPL];
__device__ float g_cls_o[Bz * Hz * CSPL * Dz];

// ===========================================================================
// Helpers
// ===========================================================================
__device__ __forceinline__ uint32_t smem_u32(const void* p) {
    uint32_t a;
    asm("{ .reg .u64 t; cvta.to.shared.u64 t, %1; cvt.u32.u64 %0, t; }"
        : "=r"(a) : "l"(p));
    return a;
}

__device__ __forceinline__ void ldsm_x4(uint32_t (&r)[4], uint32_t saddr) {
    asm volatile("ldmatrix.sync.aligned.m8n8.x4.shared.b16 {%0,%1,%2,%3}, [%4];"
        : "=r"(r[0]), "=r"(r[1]), "=r"(r[2]), "=r"(r[3]) : "r"(saddr));
}

__device__ __forceinline__ void mma_bf16(float (&c)[4], const uint32_t (&a)[4],
                                         uint32_t b0, uint32_t b1) {
    asm volatile(
        "mma.sync.aligned.m16n8k16.row.col.f32.bf16.bf16.f32 "
        "{%0,%1,%2,%3}, {%4,%5,%6,%7}, {%8,%9}, {%0,%1,%2,%3};"
        : "+f"(c[0]), "+f"(c[1]), "+f"(c[2]), "+f"(c[3])
        : "r"(a[0]), "r"(a[1]), "r"(a[2]), "r"(a[3]), "r"(b0), "r"(b1));
}

__device__ __forceinline__ void cp_async16(uint32_t dst, const void* src, bool valid) {
    asm volatile("cp.async.ca.shared.global [%0], [%1], 16, %2;"
        :: "r"(dst), "l"(src), "r"(valid ? 16 : 0) : "memory");
}
#define CP_COMMIT() asm volatile("cp.async.commit_group;" ::: "memory")
template <int N>
__device__ __forceinline__ void cp_wait() {
    asm volatile("cp.async.wait_group %0;" :: "n"(N) : "memory");
}

__device__ __forceinline__ void split1(float x, __nv_bfloat16& h, __nv_bfloat16& l) {
    h = __float2bfloat16(x);
    l = __float2bfloat16(x - __bfloat162float(h));
}
__device__ __forceinline__ void split2(float x, float y, uint32_t& hi, uint32_t& lo) {
    __nv_bfloat16 hx, lx, hy, ly;
    split1(x, hx, lx);
    split1(y, hy, ly);
    hi = (uint32_t)__bfloat16_as_ushort(hx) | ((uint32_t)__bfloat16_as_ushort(hy) << 16);
    lo = (uint32_t)__bfloat16_as_ushort(lx) | ((uint32_t)__bfloat16_as_ushort(ly) << 16);
}

// ===========================================================================
// Prep kernels: fp32 -> bf16 hi/lo (x) and hi/lo transposed (weights)
// ===========================================================================
__global__ __launch_bounds__(256) void prep_x_kernel(const float* __restrict__ x)
{
    int idx4 = blockIdx.x * 256 + threadIdx.x;
    int base = idx4 * 4;
    if (base >= Mz * Ez) return;
    float4 v = *(const float4*)(x + base);
    uint32_t h01, l01, h23, l23;
    split2(v.x, v.y, h01, l01);
    split2(v.z, v.w, h23, l23);
    *(uint2*)((char*)g_x_hi + (size_t)base * 2) = make_uint2(h01, h23);
    *(uint2*)((char*)g_x_lo + (size_t)base * 2) = make_uint2(l01, l23);
}

__global__ __launch_bounds__(256) void prep_w_kernel(
    const float* __restrict__ Wq, const float* __restrict__ Wk,
    const float* __restrict__ Wv, const float* __restrict__ Wo)
{
    const int z = blockIdx.y;
    const float* W = (z == 0) ? Wq : (z == 1) ? Wk : (z == 2) ? Wv : Wo;
    int idx = blockIdx.x * 256 + threadIdx.x;    // over [n][k], k contiguous
    if (idx >= WSZ) return;
    int n = idx / Ez, k = idx - n * Ez;
    __nv_bfloat16 h, l;
    split1(W[(size_t)k * Ez + n], h, l);
    g_Wt_hi[(size_t)z * WSZ + idx] = h;
    g_Wt_lo[(size_t)z * WSZ + idx] = l;
}

// ===========================================================================
// HMMA GEMM with cp.async 2-stage pipeline. Target 2 CTAs/SM (regs <= 128).
// ===========================================================================
#define KPAD  40
#define ARR_B 10240
#define STG_B 40960

template <int QKV>
__global__ __launch_bounds__(256, 2) void mma_gemm_kernel(
    const float* __restrict__ b0, const float* __restrict__ b1,
    const float* __restrict__ b2, const float* __restrict__ b3,
    float* __restrict__ Cout)
{
    extern __shared__ __align__(16) char smem[];
    const uint32_t sb = smem_u32(smem);

    const int tid  = threadIdx.x;
    const int wid  = tid >> 5;
    const int lane = tid & 31;
    const int bn = blockIdx.x;
    const int bm = blockIdx.y;
    const int z  = QKV ? blockIdx.z : 3;

    const __nv_bfloat16* Ah = QKV ? g_x_hi : g_attn_hi;
    const __nv_bfloat16* Al = QKV ? g_x_lo : g_attn_lo;
    const __nv_bfloat16* Bh = g_Wt_hi + (size_t)z * WSZ;
    const __nv_bfloat16* Bl = g_Wt_lo + (size_t)z * WSZ;
    const float* bias = (z == 0) ? b0 : (z == 1) ? b1 : (z == 2) ? b2 : b3;

    const int m0 = bm * 128;
    const int n0 = bn * 128;
    const int wm = wid & 3;
    const int wn = wid >> 2;

    float acc[2][8][4];
#pragma unroll
    for (int mt = 0; mt < 2; ++mt)
#pragma unroll
        for (int nt = 0; nt < 8; ++nt)
#pragma unroll
            for (int q = 0; q < 4; ++q) acc[mt][nt][q] = 0.f;

    const int srow0 = tid >> 2;
    const int scol  = (tid & 3) * 8;

    auto stage = [&](int c, int s) {
        const uint32_t s0 = sb + s * STG_B;
#pragma unroll
        for (int t = 0; t < 2; ++t) {
            const int row = srow0 + t * 64;
            const uint32_t soff = (uint32_t)(row * KPAD + scol) * 2;
            const int ga = m0 + row;
            const size_t aidx = (size_t)ga * Ez + c * 32 + scol;
            const bool av = (ga < Mz);
            cp_async16(s0 + 0 * ARR_B + soff, Ah + aidx, av);
            cp_async16(s0 + 1 * ARR_B + soff, Al + aidx, av);
            const size_t bidx = (size_t)(n0 + row) * Ez + c * 32 + scol;
            cp_async16(s0 + 2 * ARR_B + soff, Bh + bidx, true);
            cp_async16(s0 + 3 * ARR_B + soff, Bl + bidx, true);
        }
    };

    const int grp = lane >> 3;
    const int wl  = lane & 7;

    stage(0, 0);
    CP_COMMIT();

    for (int c = 0; c < 12; ++c) {
        if (c < 11) {
            stage(c + 1, (c + 1) & 1);
            CP_COMMIT();
            cp_wait<1>();
        } else {
            cp_wait<0>();
        }
        __syncthreads();

        const uint32_t s0 = sb + (c & 1) * STG_B;
        const uint32_t sA_hi = s0;
        const uint32_t sA_lo = s0 + ARR_B;
        const uint32_t sB_hi = s0 + 2 * ARR_B;
        const uint32_t sB_lo = s0 + 3 * ARR_B;

#pragma unroll
        for (int ks = 0; ks < 2; ++ks) {
            const int k0 = ks * 16;
            uint32_t ah[2][4], al[2][4];
            const int a_r = wm * 32 + wl + (grp & 1) * 8;
            const int a_k = k0 + (grp >> 1) * 8;
#pragma unroll
            for (int mt = 0; mt < 2; ++mt) {
                uint32_t off = (uint32_t)((a_r + mt * 16) * KPAD + a_k) * 2;
                ldsm_x4(ah[mt], sA_hi + off);
                ldsm_x4(al[mt], sA_lo + off);
            }
            const int b_n = wn * 64 + wl + (grp >> 1) * 8;
            const int b_k = k0 + (grp & 1) * 8;
#pragma unroll
            for (int nt2 = 0; nt2 < 4; ++nt2) {
                uint32_t bh[4], bl[4];
                uint32_t off = (uint32_t)((b_n + nt2 * 16) * KPAD + b_k) * 2;
                ldsm_x4(bh, sB_hi + off);
                ldsm_x4(bl, sB_lo + off);
#pragma unroll
                for (int mt = 0; mt < 2; ++mt) {
                    mma_bf16(acc[mt][nt2 * 2 + 0], ah[mt], bh[0], bh[1]);
                    mma_bf16(acc[mt][nt2 * 2 + 0], ah[mt], bl[0], bl[1]);
                    mma_bf16(acc[mt][nt2 * 2 + 0], al[mt], bh[0], bh[1]);
                    mma_bf16(acc[mt][nt2 * 2 + 1], ah[mt], bh[2], bh[3]);
                    mma_bf16(acc[mt][nt2 * 2 + 1], ah[mt], bl[2], bl[3]);
                    mma_bf16(acc[mt][nt2 * 2 + 1], al[mt], bh[2], bh[3]);
                }
            }
        }
        __syncthreads();
    }

    const int tq = lane >> 2;
    const int tr = lane & 3;
#pragma unroll
    for (int mt = 0; mt < 2; ++mt) {
#pragma unroll
        for (int nt = 0; nt < 8; ++nt) {
            const int gcol = n0 + wn * 64 + nt * 8 + tr * 2;
            const float bv0 = bias[gcol];
            const float bv1 = bias[gcol + 1];
#pragma unroll
            for (int half = 0; half < 2; ++half) {
                const int grow = m0 + wm * 32 + mt * 16 + tq + half * 8;
                if (grow >= Mz) continue;
                float v0 = acc[mt][nt][half * 2 + 0] + bv0;
                float v1 = acc[mt][nt][half * 2 + 1] + bv1;
                if (QKV) {
                    int b = grow / Lz, l = grow - b * Lz;
                    int h = gcol >> 6, d = gcol & 63;
                    float* dst = (z == 0) ? g_Q : (z == 1) ? g_K : g_V;
                    *(float2*)(dst + (((size_t)(b * Hz + h)) * Lz + l) * Dz + d) =
                        make_float2(v0, v1);
                } else {
                    *(float2*)(Cout + (size_t)grow * Ez + gcol) = make_float2(v0, v1);
                }
            }
        }
    }
}

// ===========================================================================
// Fused attention: grid (40, Hz, Bz) x 256 threads.
//   bx in [0,32): windowed attention for a 32-query tile
//   bx in [32,40): CLS split-K partials, two 128-thread groups = 2 splits
// Both paths hit __syncthreads() the same number of times per CTA.
// ===========================================================================
__global__ __launch_bounds__(256) void attn_kernel()
{
    const int bx = blockIdx.x;
    const int h  = blockIdx.y;
    const int b  = blockIdx.z;
    const int tid = threadIdx.x;
    const unsigned FULL = 0xffffffffu;

    __shared__ float Ks[65][64];
    __shared__ float Vs[65][64];
    // CLS path shared (per 128-thread group)
    __shared__ float c_qv[2][Dz];
    __shared__ float c_sc[2][CKEYS];
    __shared__ float c_redm[2][4];
    __shared__ float c_reds[2][4];
    __shared__ float c_oacc[2][2][Dz];

    const size_t bhbase = ((size_t)(b * Hz + h)) * Lz * Dz;

    if (bx < 32) {
        // ---------------- windowed path ----------------
        const int q0 = 1 + bx * 32;
        const float* Kbase = g_K + bhbase;
        const float* Vbase = g_V + bhbase;

        for (int i = tid; i < 65 * 16; i += 256) {
            int r = i >> 4;
            int c = (i & 15) * 4;
            int kidx = (r == 64) ? 0 : (q0 - 16 + r);
            float4 kv = make_float4(0.f, 0.f, 0.f, 0.f);
            float4 vv = kv;
            if (kidx >= 0 && kidx < Lz) {
                kv = *(const float4*)(Kbase + (size_t)kidx * Dz + c);
                vv = *(const float4*)(Vbase + (size_t)kidx * Dz + c);
            }
            *(float4*)&Ks[r][c] = kv;
            *(float4*)&Vs[r][c] = vv;
        }
        __syncthreads();

        const int warp = tid >> 5;
        const int lane = tid & 31;

        for (int i = 0; i < 4; ++i) {
            const int l = q0 + warp * 4 + i;
            const int base = l - q0;
            const float qv0 = g_Q[bhbase + (size_t)l * Dz + lane];
            const float qv1 = g_Q[bhbase + (size_t)l * Dz + lane + 32];

            float s_lo = -INFINITY;
            float s_hi = -INFINITY;

#pragma unroll
            for (int w = 0; w < 33; ++w) {
                int row = base + w;
                float v = qv0 * Ks[row][lane] + qv1 * Ks[row][lane + 32];
                v += __shfl_xor_sync(FULL, v, 16);
                v += __shfl_xor_sync(FULL, v, 8);
                v += __shfl_xor_sync(FULL, v, 4);
                v += __shfl_xor_sync(FULL, v, 2);
                v += __shfl_xor_sync(FULL, v, 1);
                int kidx = l - PADz + w;
                float scv = (kidx >= 1 && kidx < Lz) ? v * SCALE : -INFINITY;
                if (w < 32) {
                    if (lane == w) s_lo = scv;
                } else {
                    if (lane == 0) s_hi = scv;
                }
            }
            {
                float v = qv0 * Ks[64][lane] + qv1 * Ks[64][lane + 32];
                v += __shfl_xor_sync(FULL, v, 16);
                v += __shfl_xor_sync(FULL, v, 8);
                v += __shfl_xor_sync(FULL, v, 4);
                v += __shfl_xor_sync(FULL, v, 2);
                v += __shfl_xor_sync(FULL, v, 1);
                if (lane == 1) s_hi = v * SCALE;
            }

            float m = fmaxf(s_lo, s_hi);
            m = fmaxf(m, __shfl_xor_sync(FULL, m, 16));
            m = fmaxf(m, __shfl_xor_sync(FULL, m, 8));
            m = fmaxf(m, __shfl_xor_sync(FULL, m, 4));
            m = fmaxf(m, __shfl_xor_sync(FULL, m, 2));
            m = fmaxf(m, __shfl_xor_sync(FULL, m, 1));

            float p_lo = __expf(s_lo - m);
            float p_hi = (lane < 2) ? __expf(s_hi - m) : 0.f;
            float t = p_lo + p_hi;
            t += __shfl_xor_sync(FULL, t, 16);
            t += __shfl_xor_sync(FULL, t, 8);
            t += __shfl_xor_sync(FULL, t, 4);
            t += __shfl_xor_sync(FULL, t, 2);
            t += __shfl_xor_sync(FULL, t, 1);
            const float inv = 1.f / t;

            float acc0 = 0.f, acc1 = 0.f;
#pragma unroll
            for (int w = 0; w < 32; ++w) {
                float p = __shfl_sync(FULL, p_lo, w);
                int row = base + w;
                acc0 = fmaf(p, Vs[row][lane],      acc0);
                acc1 = fmaf(p, Vs[row][lane + 32], acc1);
            }
            {
                float p32 = __shfl_sync(FULL, p_hi, 0);
                acc0 = fmaf(p32, Vs[base + 32][lane],      acc0);
                acc1 = fmaf(p32, Vs[base + 32][lane + 32], acc1);
                float pc = __shfl_sync(FULL, p_hi, 1);
                acc0 = fmaf(pc, Vs[64][lane],      acc0);
                acc1 = fmaf(pc, Vs[64][lane + 32], acc1);
            }

            acc0 *= inv;
            acc1 *= inv;
            __nv_bfloat16 h0, l0, h1, l1;
            split1(acc0, h0, l0);
            split1(acc1, h1, l1);
            size_t o = ((size_t)b * Lz + l) * Ez + h * Dz;
            g_attn_hi[o + lane]      = h0;
            g_attn_lo[o + lane]      = l0;
            g_attn_hi[o + lane + 32] = h1;
            g_attn_lo[o + lane + 32] = l1;
        }
        // match cls-path extra syncthreads count (3 more below)
        __syncthreads();
        __syncthreads();
        __syncthreads();
    } else {
        // ---------------- CLS split-K path: two independent 128-groups ----
        const int grpi = tid >> 7;           // 0..1
        const int gtid = tid & 127;
        const int warp = gtid >> 5;
        const int lane = tid & 31;
        const int sp = (bx - 32) * 2 + grpi; // 0..15

        const int k0 = sp * CKEYS;
        const int nk = min(CKEYS, Lz - k0);

        if (gtid < Dz) c_qv[grpi][gtid] = g_Q[bhbase + gtid];
        __syncthreads();

        float lmax = -INFINITY;
        for (int i = warp; i < nk; i += 4) {
            const float* kr = g_K + bhbase + (size_t)(k0 + i) * Dz;
            float v = c_qv[grpi][lane] * kr[lane] + c_qv[grpi][lane + 32] * kr[lane + 32];
            v += __shfl_xor_sync(FULL, v, 16);
            v += __shfl_xor_sync(FULL, v, 8);
            v += __shfl_xor_sync(FULL, v, 4);
            v += __shfl_xor_sync(FULL, v, 2);
            v += __shfl_xor_sync(FULL, v, 1);
            v *= SCALE;
            if (lane == 0) c_sc[grpi][i] = v;
            lmax = fmaxf(lmax, v);
        }
        if (lane == 0) c_redm[grpi][warp] = lmax;
        __syncthreads();
        const float m = fmaxf(fmaxf(c_redm[grpi][0], c_redm[grpi][1]),
                              fmaxf(c_redm[grpi][2], c_redm[grpi][3]));

        float ls = 0.f;
        for (int i = gtid; i < nk; i += 128) {
            float p = __expf(c_sc[grpi][i] - m);
            c_sc[grpi][i] = p;
            ls += p;
        }
        ls += __shfl_xor_sync(FULL, ls, 16);
        ls += __shfl_xor_sync(FULL, ls, 8);
        ls += __shfl_xor_sync(FULL, ls, 4);
        ls += __shfl_xor_sync(FULL, ls, 2);
        ls += __shfl_xor_sync(FULL, ls, 1);
        if (lane == 0) c_reds[grpi][warp] = ls;
        __syncthreads();
        const float S = c_reds[grpi][0] + c_reds[grpi][1] +
                        c_reds[grpi][2] + c_reds[grpi][3];

        const int g = gtid >> 6;
        const int d = gtid & 63;
        float a = 0.f;
        for (int i = g; i < nk; i += 2)
            a = fmaf(c_sc[grpi][i], g_V[bhbase + (size_t)(k0 + i) * Dz + d], a);
        c_oacc[grpi][g][d] = a;
        __syncthreads();

        if (gtid < Dz) {
            const int idx = (b * Hz + h) * CSPL + sp;
            g_cls_o[(size_t)idx * Dz + gtid] = c_oacc[grpi][0][gtid] + c_oacc[grpi][1][gtid];
            if (gtid == 0) { g_cls_m[idx] = m; g_cls_s[idx] = S; }
        }
    }
}

// ---------------------------------------------------------------------------
// CLS combine: grid (Hz, Bz), 64 threads. Merge CSPL partials, emit bf16.
// ---------------------------------------------------------------------------
__global__ __launch_bounds__(64) void cls_comb_kernel()
{
    const int h = blockIdx.x;
    const int b = blockIdx.y;
    const int d = threadIdx.x;
    const int base = (b * Hz + h) * CSPL;

    float M = -INFINITY;
#pragma unroll
    for (int j = 0; j < CSPL; ++j) M = fmaxf(M, g_cls_m[base + j]);
    float S = 0.f, o = 0.f;
#pragma unroll
    for (int j = 0; j < CSPL; ++j) {
        float w = __expf(g_cls_m[base + j] - M);
        S = fmaf(g_cls_s[base + j], w, S);
        o = fmaf(g_cls_o[(size_t)(base + j) * Dz + d], w, o);
    }
    float acc = o / S;
    __nv_bfloat16 hh, ll;
    split1(acc, hh, ll);
    size_t off = ((size_t)b * Lz) * Ez + h * Dz + d;
    g_attn_hi[off] = hh;
    g_attn_lo[off] = ll;
}

// ---------------------------------------------------------------------------
// Launch
// ---------------------------------------------------------------------------
extern "C" void kernel_launch(void* const* d_in, const int* in_sizes, int n_in,
                              void* d_out, int out_size)
{
    const float* x  = (const float*)d_in[0];
    const float* Wq = (const float*)d_in[1];
    const float* bq = (const float*)d_in[2];
    const float* Wk = (const float*)d_in[3];
    const float* bk = (const float*)d_in[4];
    const float* Wv = (const float*)d_in[5];
    const float* bv = (const float*)d_in[6];
    const float* Wo = (const float*)d_in[7];
    const float* bo = (const float*)d_in[8];
    float* out = (float*)d_out;

    static bool attr_done = false;
    if (!attr_done) {
        cudaFuncSetAttribute((const void*)mma_gemm_kernel<1>,
                             cudaFuncAttributeMaxDynamicSharedMemorySize, 2 * STG_B);
        cudaFuncSetAttribute((const void*)mma_gemm_kernel<0>,
                             cudaFuncAttributeMaxDynamicSharedMemorySize, 2 * STG_B);
        attr_done = true;
    }

    prep_x_kernel<<<(Mz * Ez / 4 + 255) / 256, 256>>>(x);
    prep_w_kernel<<<dim3((WSZ + 255) / 256, 4), 256>>>(Wq, Wk, Wv, Wo);

    dim3 gridQKV(Ez / 128, (Mz + 127) / 128, 3);   // 585 CTAs
    dim3 gridO(Ez / 128, (Mz + 127) / 128);        // 195 CTAs

    mma_gemm_kernel<1><<<gridQKV, 256, 2 * STG_B>>>(bq, bk, bv, bo, nullptr);

    attn_kernel<<<dim3(40, Hz, Bz), 256>>>();      // window + CLS partials fused
    cls_comb_kernel<<<dim3(Hz, Bz), 64>>>();

    mma_gemm_kernel<0><<<gridO, 256, 2 * STG_B>>>(bq, bk, bv, bo, out);
}

// round 8
// speedup vs baseline: 2.7198x; 1.0773x over previous
#include <cuda_runtime.h>
#include <cuda_bf16.h>
#include <math.h>
#include <cstdint>

// Problem constants
#define Bz   8
#define Lz   1025
#define Ez   384
#define Hz   6
#define Dz   64
#define PADz 16
#define Mz   (Bz * Lz)          // 8200 rows
#define SCALE 0.125f
#define WSZ  (Ez * Ez)          // 147456

// CLS split-K attention
#define CSPL  16
#define CKEYS 65                // ceil(1025/16)

// Scratch (device globals; no runtime allocation allowed)
__device__ float g_Q[Bz * Hz * Lz * Dz];
__device__ float g_K[Bz * Hz * Lz * Dz];
__device__ float g_V[Bz * Hz * Lz * Dz];
__device__ __nv_bfloat16 g_x_hi[Mz * Ez];
__device__ __nv_bfloat16 g_x_lo[Mz * Ez];
__device__ __nv_bfloat16 g_attn_hi[Mz * Ez];
__device__ __nv_bfloat16 g_attn_lo[Mz * Ez];
__device__ __nv_bfloat16 g_Wt_hi[4 * WSZ];   // transposed [z][n][k]
__device__ __nv_bfloat16 g_Wt_lo[4 * WSZ];
__device__ float g_cls_m[Bz * Hz * CSPL];
__device__ float g_cls_s[Bz * Hz * CSPL];
__device__ float g_cls_o[Bz * Hz * CSPL * Dz];

// ===========================================================================
// Helpers
// ===========================================================================
__device__ __forceinline__ uint32_t smem_u32(const void* p) {
    uint32_t a;
    asm("{ .reg .u64 t; cvta.to.shared.u64 t, %1; cvt.u32.u64 %0, t; }"
        : "=r"(a) : "l"(p));
    return a;
}

__device__ __forceinline__ void ldsm_x4(uint32_t (&r)[4], uint32_t saddr) {
    asm volatile("ldmatrix.sync.aligned.m8n8.x4.shared.b16 {%0,%1,%2,%3}, [%4];"
        : "=r"(r[0]), "=r"(r[1]), "=r"(r[2]), "=r"(r[3]) : "r"(saddr));
}

__device__ __forceinline__ void mma_bf16(float (&c)[4], const uint32_t (&a)[4],
                                         uint32_t b0, uint32_t b1) {
    asm volatile(
        "mma.sync.aligned.m16n8k16.row.col.f32.bf16.bf16.f32 "
        "{%0,%1,%2,%3}, {%4,%5,%6,%7}, {%8,%9}, {%0,%1,%2,%3};"
        : "+f"(c[0]), "+f"(c[1]), "+f"(c[2]), "+f"(c[3])
        : "r"(a[0]), "r"(a[1]), "r"(a[2]), "r"(a[3]), "r"(b0), "r"(b1));
}

__device__ __forceinline__ void cp_async16(uint32_t dst, const void* src, bool valid) {
    asm volatile("cp.async.ca.shared.global [%0], [%1], 16, %2;"
        :: "r"(dst), "l"(src), "r"(valid ? 16 : 0) : "memory");
}
#define CP_COMMIT() asm volatile("cp.async.commit_group;" ::: "memory")
template <int N>
__device__ __forceinline__ void cp_wait() {
    asm volatile("cp.async.wait_group %0;" :: "n"(N) : "memory");
}

__device__ __forceinline__ void split1(float x, __nv_bfloat16& h, __nv_bfloat16& l) {
    h = __float2bfloat16(x);
    l = __float2bfloat16(x - __bfloat162float(h));
}
__device__ __forceinline__ void split2(float x, float y, uint32_t& hi, uint32_t& lo) {
    __nv_bfloat16 hx, lx, hy, ly;
    split1(x, hx, lx);
    split1(y, hy, ly);
    hi = (uint32_t)__bfloat16_as_ushort(hx) | ((uint32_t)__bfloat16_as_ushort(hy) << 16);
    lo = (uint32_t)__bfloat16_as_ushort(lx) | ((uint32_t)__bfloat16_as_ushort(ly) << 16);
}

// ===========================================================================
// Prep kernels
// ===========================================================================
__global__ __launch_bounds__(256) void prep_x_kernel(const float* __restrict__ x)
{
    int idx4 = blockIdx.x * 256 + threadIdx.x;
    int base = idx4 * 4;
    if (base >= Mz * Ez) return;
    float4 v = *(const float4*)(x + base);
    uint32_t h01, l01, h23, l23;
    split2(v.x, v.y, h01, l01);
    split2(v.z, v.w, h23, l23);
    *(uint2*)((char*)g_x_hi + (size_t)base * 2) = make_uint2(h01, h23);
    *(uint2*)((char*)g_x_lo + (size_t)base * 2) = make_uint2(l01, l23);
}

__global__ __launch_bounds__(256) void prep_w_kernel(
    const float* __restrict__ Wq, const float* __restrict__ Wk,
    const float* __restrict__ Wv, const float* __restrict__ Wo)
{
    const int z = blockIdx.y;
    const float* W = (z == 0) ? Wq : (z == 1) ? Wk : (z == 2) ? Wv : Wo;
    int idx = blockIdx.x * 256 + threadIdx.x;
    if (idx >= WSZ) return;
    int n = idx / Ez, k = idx - n * Ez;
    __nv_bfloat16 h, l;
    split1(W[(size_t)k * Ez + n], h, l);
    g_Wt_hi[(size_t)z * WSZ + idx] = h;
    g_Wt_lo[(size_t)z * WSZ + idx] = l;
}

// ===========================================================================
// HMMA GEMM with cp.async 2-stage pipeline (unchanged from R7).
// ===========================================================================
#define KPAD  40
#define ARR_B 10240
#define STG_B 40960

template <int QKV>
__global__ __launch_bounds__(256, 2) void mma_gemm_kernel(
    const float* __restrict__ b0, const float* __restrict__ b1,
    const float* __restrict__ b2, const float* __restrict__ b3,
    float* __restrict__ Cout)
{
    extern __shared__ __align__(16) char smem[];
    const uint32_t sb = smem_u32(smem);

    const int tid  = threadIdx.x;
    const int wid  = tid >> 5;
    const int lane = tid & 31;
    const int bn = blockIdx.x;
    const int bm = blockIdx.y;
    const int z  = QKV ? blockIdx.z : 3;

    const __nv_bfloat16* Ah = QKV ? g_x_hi : g_attn_hi;
    const __nv_bfloat16* Al = QKV ? g_x_lo : g_attn_lo;
    const __nv_bfloat16* Bh = g_Wt_hi + (size_t)z * WSZ;
    const __nv_bfloat16* Bl = g_Wt_lo + (size_t)z * WSZ;
    const float* bias = (z == 0) ? b0 : (z == 1) ? b1 : (z == 2) ? b2 : b3;

    const int m0 = bm * 128;
    const int n0 = bn * 128;
    const int wm = wid & 3;
    const int wn = wid >> 2;

    float acc[2][8][4];
#pragma unroll
    for (int mt = 0; mt < 2; ++mt)
#pragma unroll
        for (int nt = 0; nt < 8; ++nt)
#pragma unroll
            for (int q = 0; q < 4; ++q) acc[mt][nt][q] = 0.f;

    const int srow0 = tid >> 2;
    const int scol  = (tid & 3) * 8;

    auto stage = [&](int c, int s) {
        const uint32_t s0 = sb + s * STG_B;
#pragma unroll
        for (int t = 0; t < 2; ++t) {
            const int row = srow0 + t * 64;
            const uint32_t soff = (uint32_t)(row * KPAD + scol) * 2;
            const int ga = m0 + row;
            const size_t aidx = (size_t)ga * Ez + c * 32 + scol;
            const bool av = (ga < Mz);
            cp_async16(s0 + 0 * ARR_B + soff, Ah + aidx, av);
            cp_async16(s0 + 1 * ARR_B + soff, Al + aidx, av);
            const size_t bidx = (size_t)(n0 + row) * Ez + c * 32 + scol;
            cp_async16(s0 + 2 * ARR_B + soff, Bh + bidx, true);
            cp_async16(s0 + 3 * ARR_B + soff, Bl + bidx, true);
        }
    };

    const int grp = lane >> 3;
    const int wl  = lane & 7;

    stage(0, 0);
    CP_COMMIT();

    for (int c = 0; c < 12; ++c) {
        if (c < 11) {
            stage(c + 1, (c + 1) & 1);
            CP_COMMIT();
            cp_wait<1>();
        } else {
            cp_wait<0>();
        }
        __syncthreads();

        const uint32_t s0 = sb + (c & 1) * STG_B;
        const uint32_t sA_hi = s0;
        const uint32_t sA_lo = s0 + ARR_B;
        const uint32_t sB_hi = s0 + 2 * ARR_B;
        const uint32_t sB_lo = s0 + 3 * ARR_B;

#pragma unroll
        for (int ks = 0; ks < 2; ++ks) {
            const int k0 = ks * 16;
            uint32_t ah[2][4], al[2][4];
            const int a_r = wm * 32 + wl + (grp & 1) * 8;
            const int a_k = k0 + (grp >> 1) * 8;
#pragma unroll
            for (int mt = 0; mt < 2; ++mt) {
                uint32_t off = (uint32_t)((a_r + mt * 16) * KPAD + a_k) * 2;
                ldsm_x4(ah[mt], sA_hi + off);
                ldsm_x4(al[mt], sA_lo + off);
            }
            const int b_n = wn * 64 + wl + (grp >> 1) * 8;
            const int b_k = k0 + (grp & 1) * 8;
#pragma unroll
            for (int nt2 = 0; nt2 < 4; ++nt2) {
                uint32_t bh[4], bl[4];
                uint32_t off = (uint32_t)((b_n + nt2 * 16) * KPAD + b_k) * 2;
                ldsm_x4(bh, sB_hi + off);
                ldsm_x4(bl, sB_lo + off);
#pragma unroll
                for (int mt = 0; mt < 2; ++mt) {
                    mma_bf16(acc[mt][nt2 * 2 + 0], ah[mt], bh[0], bh[1]);
                    mma_bf16(acc[mt][nt2 * 2 + 0], ah[mt], bl[0], bl[1]);
                    mma_bf16(acc[mt][nt2 * 2 + 0], al[mt], bh[0], bh[1]);
                    mma_bf16(acc[mt][nt2 * 2 + 1], ah[mt], bh[2], bh[3]);
                    mma_bf16(acc[mt][nt2 * 2 + 1], ah[mt], bl[2], bl[3]);
                    mma_bf16(acc[mt][nt2 * 2 + 1], al[mt], bh[2], bh[3]);
                }
            }
        }
        __syncthreads();
    }

    const int tq = lane >> 2;
    const int tr = lane & 3;
#pragma unroll
    for (int mt = 0; mt < 2; ++mt) {
#pragma unroll
        for (int nt = 0; nt < 8; ++nt) {
            const int gcol = n0 + wn * 64 + nt * 8 + tr * 2;
            const float bv0 = bias[gcol];
            const float bv1 = bias[gcol + 1];
#pragma unroll
            for (int half = 0; half < 2; ++half) {
                const int grow = m0 + wm * 32 + mt * 16 + tq + half * 8;
                if (grow >= Mz) continue;
                float v0 = acc[mt][nt][half * 2 + 0] + bv0;
                float v1 = acc[mt][nt][half * 2 + 1] + bv1;
                if (QKV) {
                    int b = grow / Lz, l = grow - b * Lz;
                    int h = gcol >> 6, d = gcol & 63;
                    float* dst = (z == 0) ? g_Q : (z == 1) ? g_K : g_V;
                    *(float2*)(dst + (((size_t)(b * Hz + h)) * Lz + l) * Dz + d) =
                        make_float2(v0, v1);
                } else {
                    *(float2*)(Cout + (size_t)grow * Ez + gcol) = make_float2(v0, v1);
                }
            }
        }
    }
}

// ===========================================================================
// Fused attention: grid (40, Hz, Bz) x 256 threads.
//   bx in [0,32): windowed attention, LSU-optimized:
//     scores: per-lane full dots (no reduction shuffles), Ks padded to 68
//     V: single pass over the warp's 37-row union, shared by 4 queries
//   bx in [32,40): CLS split-K partials (two 128-thread groups)
// Both paths execute the same number of __syncthreads().
// ===========================================================================
#define KPADF 68

__global__ __launch_bounds__(256) void attn_kernel()
{
    const int bx = blockIdx.x;
    const int h  = blockIdx.y;
    const int b  = blockIdx.z;
    const int tid = threadIdx.x;
    const unsigned FULL = 0xffffffffu;

    __shared__ float Ks[65][KPADF];
    __shared__ float Vs[65][64];
    __shared__ float Qs[32][64];
    // CLS path shared (per 128-thread group)
    __shared__ float c_qv[2][Dz];
    __shared__ float c_sc[2][CKEYS];
    __shared__ float c_redm[2][4];
    __shared__ float c_reds[2][4];
    __shared__ float c_oacc[2][2][Dz];

    const size_t bhbase = ((size_t)(b * Hz + h)) * Lz * Dz;

    if (bx < 32) {
        // ---------------- windowed path ----------------
        const int q0 = 1 + bx * 32;
        const float* Kbase = g_K + bhbase;
        const float* Vbase = g_V + bhbase;

        for (int i = tid; i < 65 * 16; i += 256) {
            int r = i >> 4;
            int c = (i & 15) * 4;
            int kidx = (r == 64) ? 0 : (q0 - 16 + r);
            float4 kv = make_float4(0.f, 0.f, 0.f, 0.f);
            float4 vv = kv;
            if (kidx >= 0 && kidx < Lz) {
                kv = *(const float4*)(Kbase + (size_t)kidx * Dz + c);
                vv = *(const float4*)(Vbase + (size_t)kidx * Dz + c);
            }
            *(float4*)&Ks[r][c] = kv;
            *(float4*)&Vs[r][c] = vv;
        }
        for (int i = tid; i < 32 * 16; i += 256) {
            int r = i >> 4;
            int c = (i & 15) * 4;
            *(float4*)&Qs[r][c] =
                *(const float4*)(g_Q + bhbase + (size_t)(q0 + r) * Dz + c);
        }
        __syncthreads();

        const int warp = tid >> 5;
        const int lane = tid & 31;
        const int base0 = warp * 4;          // tile-row of this warp's 1st query

        float pq[4], phi[4], inv[4];

#pragma unroll
        for (int i = 0; i < 4; ++i) {
            const int ql = base0 + i;        // 0..31
            const int l  = q0 + ql;          // global query index
            const int row  = ql + lane;      // key row for window pos w = lane
            const int row2 = (lane == 0) ? (ql + 32) : 64;  // w32 / CLS

            float s0 = 0.f, s1 = 0.f, s2 = 0.f, s3 = 0.f;
            float t0 = 0.f, t1 = 0.f, t2 = 0.f, t3 = 0.f;
#pragma unroll
            for (int dg = 0; dg < 16; ++dg) {
                float4 q4  = *(const float4*)&Qs[ql][dg * 4];
                float4 k4  = *(const float4*)&Ks[row][dg * 4];
                float4 k24 = *(const float4*)&Ks[row2][dg * 4];
                s0 = fmaf(q4.x, k4.x,  s0);
                s1 = fmaf(q4.y, k4.y,  s1);
                s2 = fmaf(q4.z, k4.z,  s2);
                s3 = fmaf(q4.w, k4.w,  s3);
                t0 = fmaf(q4.x, k24.x, t0);
                t1 = fmaf(q4.y, k24.y, t1);
                t2 = fmaf(q4.z, k24.z, t2);
                t3 = fmaf(q4.w, k24.w, t3);
            }
            float sv = (s0 + s1) + (s2 + s3);
            float tv = (t0 + t1) + (t2 + t3);

            const int kidx = l - PADz + lane;
            float s_lo = (kidx >= 1 && kidx < Lz) ? sv * SCALE : -INFINITY;
            float s_hi = -INFINITY;
            if (lane == 0) s_hi = (l + PADz < Lz) ? tv * SCALE : -INFINITY;
            if (lane == 1) s_hi = tv * SCALE;       // CLS always valid

            float m = fmaxf(s_lo, s_hi);
            m = fmaxf(m, __shfl_xor_sync(FULL, m, 16));
            m = fmaxf(m, __shfl_xor_sync(FULL, m, 8));
            m = fmaxf(m, __shfl_xor_sync(FULL, m, 4));
            m = fmaxf(m, __shfl_xor_sync(FULL, m, 2));
            m = fmaxf(m, __shfl_xor_sync(FULL, m, 1));

            float p  = __expf(s_lo - m);
            float ph = (lane < 2) ? __expf(s_hi - m) : 0.f;
            float t = p + ph;
            t += __shfl_xor_sync(FULL, t, 16);
            t += __shfl_xor_sync(FULL, t, 8);
            t += __shfl_xor_sync(FULL, t, 4);
            t += __shfl_xor_sync(FULL, t, 2);
            t += __shfl_xor_sync(FULL, t, 1);

            pq[i]  = p;
            phi[i] = ph;
            inv[i] = 1.f / t;
        }

        // ---- V accumulation: one pass over the 36-row union + CLS ----
        float a0[4] = {0.f, 0.f, 0.f, 0.f};
        float a1[4] = {0.f, 0.f, 0.f, 0.f};
#pragma unroll 4
        for (int j = 0; j < 36; ++j) {
            const int row = base0 + j;
            const float v0 = Vs[row][lane];
            const float v1 = Vs[row][lane + 32];
#pragma unroll
            for (int i = 0; i < 4; ++i) {
                const int w = j - i;                 // window pos for query i
                const bool valid = (w >= 0) && (w <= 32);
                float src = (w < 32) ? pq[i] : phi[i];
                float pp = __shfl_sync(FULL, src, (w >= 0 && w < 32) ? w : 0);
                pp = valid ? pp : 0.f;
                a0[i] = fmaf(pp, v0, a0[i]);
                a1[i] = fmaf(pp, v1, a1[i]);
            }
        }
        {   // CLS row
            const float v0 = Vs[64][lane];
            const float v1 = Vs[64][lane + 32];
#pragma unroll
            for (int i = 0; i < 4; ++i) {
                float pc = __shfl_sync(FULL, phi[i], 1);
                a0[i] = fmaf(pc, v0, a0[i]);
                a1[i] = fmaf(pc, v1, a1[i]);
            }
        }

#pragma unroll
        for (int i = 0; i < 4; ++i) {
            const int l = q0 + base0 + i;
            float o0 = a0[i] * inv[i];
            float o1 = a1[i] * inv[i];
            __nv_bfloat16 h0, l0, h1, l1;
            split1(o0, h0, l0);
            split1(o1, h1, l1);
            size_t o = ((size_t)b * Lz + l) * Ez + h * Dz;
            g_attn_hi[o + lane]      = h0;
            g_attn_lo[o + lane]      = l0;
            g_attn_hi[o + lane + 32] = h1;
            g_attn_lo[o + lane + 32] = l1;
        }
        // match cls-path syncthreads count (3 more)
        __syncthreads();
        __syncthreads();
        __syncthreads();
    } else {
        // ---------------- CLS split-K path: two independent 128-groups ----
        const int grpi = tid >> 7;
        const int gtid = tid & 127;
        const int warp = gtid >> 5;
        const int lane = tid & 31;
        const int sp = (bx - 32) * 2 + grpi;

        const int k0 = sp * CKEYS;
        const int nk = min(CKEYS, Lz - k0);

        if (gtid < Dz) c_qv[grpi][gtid] = g_Q[bhbase + gtid];
        __syncthreads();

        float lmax = -INFINITY;
        for (int i = warp; i < nk; i += 4) {
            const float* kr = g_K + bhbase + (size_t)(k0 + i) * Dz;
            float v = c_qv[grpi][lane] * kr[lane] + c_qv[grpi][lane + 32] * kr[lane + 32];
            v += __shfl_xor_sync(FULL, v, 16);
            v += __shfl_xor_sync(FULL, v, 8);
            v += __shfl_xor_sync(FULL, v, 4);
            v += __shfl_xor_sync(FULL, v, 2);
            v += __shfl_xor_sync(FULL, v, 1);
            v *= SCALE;
            if (lane == 0) c_sc[grpi][i] = v;
            lmax = fmaxf(lmax, v);
        }
        if (lane == 0) c_redm[grpi][warp] = lmax;
        __syncthreads();
        const float m = fmaxf(fmaxf(c_redm[grpi][0], c_redm[grpi][1]),
                              fmaxf(c_redm[grpi][2], c_redm[grpi][3]));

        float ls = 0.f;
        for (int i = gtid; i < nk; i += 128) {
            float p = __expf(c_sc[grpi][i] - m);
            c_sc[grpi][i] = p;
            ls += p;
        }
        ls += __shfl_xor_sync(FULL, ls, 16);
        ls += __shfl_xor_sync(FULL, ls, 8);
        ls += __shfl_xor_sync(FULL, ls, 4);
        ls += __shfl_xor_sync(FULL, ls, 2);
        ls += __shfl_xor_sync(FULL, ls, 1);
        if (lane == 0) c_reds[grpi][warp] = ls;
        __syncthreads();
        const float S = c_reds[grpi][0] + c_reds[grpi][1] +
                        c_reds[grpi][2] + c_reds[grpi][3];

        const int g = gtid >> 6;
        const int d = gtid & 63;
        float a = 0.f;
        for (int i = g; i < nk; i += 2)
            a = fmaf(c_sc[grpi][i], g_V[bhbase + (size_t)(k0 + i) * Dz + d], a);
        c_oacc[grpi][g][d] = a;
        __syncthreads();

        if (gtid < Dz) {
            const int idx = (b * Hz + h) * CSPL + sp;
            g_cls_o[(size_t)idx * Dz + gtid] = c_oacc[grpi][0][gtid] + c_oacc[grpi][1][gtid];
            if (gtid == 0) { g_cls_m[idx] = m; g_cls_s[idx] = S; }
        }
    }
}

// ---------------------------------------------------------------------------
// CLS combine: grid (Hz, Bz), 64 threads. Merge CSPL partials, emit bf16.
// ---------------------------------------------------------------------------
__global__ __launch_bounds__(64) void cls_comb_kernel()
{
    const int h = blockIdx.x;
    const int b = blockIdx.y;
    const int d = threadIdx.x;
    const int base = (b * Hz + h) * CSPL;

    float M = -INFINITY;
#pragma unroll
    for (int j = 0; j < CSPL; ++j) M = fmaxf(M, g_cls_m[base + j]);
    float S = 0.f, o = 0.f;
#pragma unroll
    for (int j = 0; j < CSPL; ++j) {
        float w = __expf(g_cls_m[base + j] - M);
        S = fmaf(g_cls_s[base + j], w, S);
        o = fmaf(g_cls_o[(size_t)(base + j) * Dz + d], w, o);
    }
    float acc = o / S;
    __nv_bfloat16 hh, ll;
    split1(acc, hh, ll);
    size_t off = ((size_t)b * Lz) * Ez + h * Dz + d;
    g_attn_hi[off] = hh;
    g_attn_lo[off] = ll;
}

// ---------------------------------------------------------------------------
// Launch
// ---------------------------------------------------------------------------
extern "C" void kernel_launch(void* const* d_in, const int* in_sizes, int n_in,
                              void* d_out, int out_size)
{
    const float* x  = (const float*)d_in[0];
    const float* Wq = (const float*)d_in[1];
    const float* bq = (const float*)d_in[2];
    const float* Wk = (const float*)d_in[3];
    const float* bk = (const float*)d_in[4];
    const float* Wv = (const float*)d_in[5];
    const float* bv = (const float*)d_in[6];
    const float* Wo = (const float*)d_in[7];
    const float* bo = (const float*)d_in[8];
    float* out = (float*)d_out;

    static bool attr_done = false;
    if (!attr_done) {
        cudaFuncSetAttribute((const void*)mma_gemm_kernel<1>,
                             cudaFuncAttributeMaxDynamicSharedMemorySize, 2 * STG_B);
        cudaFuncSetAttribute((const void*)mma_gemm_kernel<0>,
                             cudaFuncAttributeMaxDynamicSharedMemorySize, 2 * STG_B);
        attr_done = true;
    }

    prep_x_kernel<<<(Mz * Ez / 4 + 255) / 256, 256>>>(x);
    prep_w_kernel<<<dim3((WSZ + 255) / 256, 4), 256>>>(Wq, Wk, Wv, Wo);

    dim3 gridQKV(Ez / 128, (Mz + 127) / 128, 3);   // 585 CTAs
    dim3 gridO(Ez / 128, (Mz + 127) / 128);        // 195 CTAs

    mma_gemm_kernel<1><<<gridQKV, 256, 2 * STG_B>>>(bq, bk, bv, bo, nullptr);

    attn_kernel<<<dim3(40, Hz, Bz), 256>>>();      // window + CLS partials fused
    cls_comb_kernel<<<dim3(Hz, Bz), 64>>>();

    mma_gemm_kernel<0><<<gridO, 256, 2 * STG_B>>>(bq, bk, bv, bo, out);
}

// round 9
// speedup vs baseline: 2.7834x; 1.0234x over previous
#include <cuda_runtime.h>
#include <cuda_bf16.h>
#include <math.h>
#include <cstdint>

// Problem constants
#define Bz   8
#define Lz   1025
#define Ez   384
#define Hz   6
#define Dz   64
#define PADz 16
#define Mz   (Bz * Lz)          // 8200 rows
#define SCALE 0.125f
#define WSZ  (Ez * Ez)          // 147456

// CLS split-K attention
#define CSPL  16
#define CKEYS 65                // ceil(1025/16)

// Scratch (device globals; no runtime allocation allowed)
__device__ float g_Q[Bz * Hz * Lz * Dz];
__device__ float g_K[Bz * Hz * Lz * Dz];
__device__ float g_V[Bz * Hz * Lz * Dz];
__device__ __nv_bfloat16 g_x_hi[Mz * Ez];
__device__ __nv_bfloat16 g_x_lo[Mz * Ez];
__device__ __nv_bfloat16 g_attn_hi[Mz * Ez];
__device__ __nv_bfloat16 g_attn_lo[Mz * Ez];
__device__ __nv_bfloat16 g_Wt_hi[4 * WSZ];   // transposed [z][n][k]
__device__ __nv_bfloat16 g_Wt_lo[4 * WSZ];
__device__ float g_cls_m[Bz * Hz * CSPL];
__device__ float g_cls_s[Bz * Hz * CSPL];
__device__ float g_cls_o[Bz * Hz * CSPL * Dz];

// ===========================================================================
// Helpers
// ===========================================================================
__device__ __forceinline__ uint32_t smem_u32(const void* p) {
    uint32_t a;
    asm("{ .reg .u64 t; cvta.to.shared.u64 t, %1; cvt.u32.u64 %0, t; }"
        : "=r"(a) : "l"(p));
    return a;
}

__device__ __forceinline__ void ldsm_x4(uint32_t (&r)[4], uint32_t saddr) {
    asm volatile("ldmatrix.sync.aligned.m8n8.x4.shared.b16 {%0,%1,%2,%3}, [%4];"
        : "=r"(r[0]), "=r"(r[1]), "=r"(r[2]), "=r"(r[3]) : "r"(saddr));
}

__device__ __forceinline__ void mma_bf16(float (&c)[4], const uint32_t (&a)[4],
                                         uint32_t b0, uint32_t b1) {
    asm volatile(
        "mma.sync.aligned.m16n8k16.row.col.f32.bf16.bf16.f32 "
        "{%0,%1,%2,%3}, {%4,%5,%6,%7}, {%8,%9}, {%0,%1,%2,%3};"
        : "+f"(c[0]), "+f"(c[1]), "+f"(c[2]), "+f"(c[3])
        : "r"(a[0]), "r"(a[1]), "r"(a[2]), "r"(a[3]), "r"(b0), "r"(b1));
}

__device__ __forceinline__ void cp_async16(uint32_t dst, const void* src, bool valid) {
    asm volatile("cp.async.ca.shared.global [%0], [%1], 16, %2;"
        :: "r"(dst), "l"(src), "r"(valid ? 16 : 0) : "memory");
}
#define CP_COMMIT() asm volatile("cp.async.commit_group;" ::: "memory")
template <int N>
__device__ __forceinline__ void cp_wait() {
    asm volatile("cp.async.wait_group %0;" :: "n"(N) : "memory");
}

__device__ __forceinline__ void split1(float x, __nv_bfloat16& h, __nv_bfloat16& l) {
    h = __float2bfloat16(x);
    l = __float2bfloat16(x - __bfloat162float(h));
}
__device__ __forceinline__ void split2(float x, float y, uint32_t& hi, uint32_t& lo) {
    __nv_bfloat16 hx, lx, hy, ly;
    split1(x, hx, lx);
    split1(y, hy, ly);
    hi = (uint32_t)__bfloat16_as_ushort(hx) | ((uint32_t)__bfloat16_as_ushort(hy) << 16);
    lo = (uint32_t)__bfloat16_as_ushort(lx) | ((uint32_t)__bfloat16_as_ushort(ly) << 16);
}

// ===========================================================================
// Prep kernels
// ===========================================================================
__global__ __launch_bounds__(256) void prep_x_kernel(const float* __restrict__ x)
{
    int idx4 = blockIdx.x * 256 + threadIdx.x;
    int base = idx4 * 4;
    if (base >= Mz * Ez) return;
    float4 v = *(const float4*)(x + base);
    uint32_t h01, l01, h23, l23;
    split2(v.x, v.y, h01, l01);
    split2(v.z, v.w, h23, l23);
    *(uint2*)((char*)g_x_hi + (size_t)base * 2) = make_uint2(h01, h23);
    *(uint2*)((char*)g_x_lo + (size_t)base * 2) = make_uint2(l01, l23);
}

__global__ __launch_bounds__(256) void prep_w_kernel(
    const float* __restrict__ Wq, const float* __restrict__ Wk,
    const float* __restrict__ Wv, const float* __restrict__ Wo)
{
    const int z = blockIdx.y;
    const float* W = (z == 0) ? Wq : (z == 1) ? Wk : (z == 2) ? Wv : Wo;
    int idx = blockIdx.x * 256 + threadIdx.x;
    if (idx >= WSZ) return;
    int n = idx / Ez, k = idx - n * Ez;
    __nv_bfloat16 h, l;
    split1(W[(size_t)k * Ez + n], h, l);
    g_Wt_hi[(size_t)z * WSZ + idx] = h;
    g_Wt_lo[(size_t)z * WSZ + idx] = l;
}

// ===========================================================================
// HMMA GEMM with cp.async 2-stage pipeline (unchanged).
// ===========================================================================
#define KPAD  40
#define ARR_B 10240
#define STG_B 40960

template <int QKV>
__global__ __launch_bounds__(256, 2) void mma_gemm_kernel(
    const float* __restrict__ b0, const float* __restrict__ b1,
    const float* __restrict__ b2, const float* __restrict__ b3,
    float* __restrict__ Cout)
{
    extern __shared__ __align__(16) char smem[];
    const uint32_t sb = smem_u32(smem);

    const int tid  = threadIdx.x;
    const int wid  = tid >> 5;
    const int lane = tid & 31;
    const int bn = blockIdx.x;
    const int bm = blockIdx.y;
    const int z  = QKV ? blockIdx.z : 3;

    const __nv_bfloat16* Ah = QKV ? g_x_hi : g_attn_hi;
    const __nv_bfloat16* Al = QKV ? g_x_lo : g_attn_lo;
    const __nv_bfloat16* Bh = g_Wt_hi + (size_t)z * WSZ;
    const __nv_bfloat16* Bl = g_Wt_lo + (size_t)z * WSZ;
    const float* bias = (z == 0) ? b0 : (z == 1) ? b1 : (z == 2) ? b2 : b3;

    const int m0 = bm * 128;
    const int n0 = bn * 128;
    const int wm = wid & 3;
    const int wn = wid >> 2;

    float acc[2][8][4];
#pragma unroll
    for (int mt = 0; mt < 2; ++mt)
#pragma unroll
        for (int nt = 0; nt < 8; ++nt)
#pragma unroll
            for (int q = 0; q < 4; ++q) acc[mt][nt][q] = 0.f;

    const int srow0 = tid >> 2;
    const int scol  = (tid & 3) * 8;

    auto stage = [&](int c, int s) {
        const uint32_t s0 = sb + s * STG_B;
#pragma unroll
        for (int t = 0; t < 2; ++t) {
            const int row = srow0 + t * 64;
            const uint32_t soff = (uint32_t)(row * KPAD + scol) * 2;
            const int ga = m0 + row;
            const size_t aidx = (size_t)ga * Ez + c * 32 + scol;
            const bool av = (ga < Mz);
            cp_async16(s0 + 0 * ARR_B + soff, Ah + aidx, av);
            cp_async16(s0 + 1 * ARR_B + soff, Al + aidx, av);
            const size_t bidx = (size_t)(n0 + row) * Ez + c * 32 + scol;
            cp_async16(s0 + 2 * ARR_B + soff, Bh + bidx, true);
            cp_async16(s0 + 3 * ARR_B + soff, Bl + bidx, true);
        }
    };

    const int grp = lane >> 3;
    const int wl  = lane & 7;

    stage(0, 0);
    CP_COMMIT();

    for (int c = 0; c < 12; ++c) {
        if (c < 11) {
            stage(c + 1, (c + 1) & 1);
            CP_COMMIT();
            cp_wait<1>();
        } else {
            cp_wait<0>();
        }
        __syncthreads();

        const uint32_t s0 = sb + (c & 1) * STG_B;
        const uint32_t sA_hi = s0;
        const uint32_t sA_lo = s0 + ARR_B;
        const uint32_t sB_hi = s0 + 2 * ARR_B;
        const uint32_t sB_lo = s0 + 3 * ARR_B;

#pragma unroll
        for (int ks = 0; ks < 2; ++ks) {
            const int k0 = ks * 16;
            uint32_t ah[2][4], al[2][4];
            const int a_r = wm * 32 + wl + (grp & 1) * 8;
            const int a_k = k0 + (grp >> 1) * 8;
#pragma unroll
            for (int mt = 0; mt < 2; ++mt) {
                uint32_t off = (uint32_t)((a_r + mt * 16) * KPAD + a_k) * 2;
                ldsm_x4(ah[mt], sA_hi + off);
                ldsm_x4(al[mt], sA_lo + off);
            }
            const int b_n = wn * 64 + wl + (grp >> 1) * 8;
            const int b_k = k0 + (grp & 1) * 8;
#pragma unroll
            for (int nt2 = 0; nt2 < 4; ++nt2) {
                uint32_t bh[4], bl[4];
                uint32_t off = (uint32_t)((b_n + nt2 * 16) * KPAD + b_k) * 2;
                ldsm_x4(bh, sB_hi + off);
                ldsm_x4(bl, sB_lo + off);
#pragma unroll
                for (int mt = 0; mt < 2; ++mt) {
                    mma_bf16(acc[mt][nt2 * 2 + 0], ah[mt], bh[0], bh[1]);
                    mma_bf16(acc[mt][nt2 * 2 + 0], ah[mt], bl[0], bl[1]);
                    mma_bf16(acc[mt][nt2 * 2 + 0], al[mt], bh[0], bh[1]);
                    mma_bf16(acc[mt][nt2 * 2 + 1], ah[mt], bh[2], bh[3]);
                    mma_bf16(acc[mt][nt2 * 2 + 1], ah[mt], bl[2], bl[3]);
                    mma_bf16(acc[mt][nt2 * 2 + 1], al[mt], bh[2], bh[3]);
                }
            }
        }
        __syncthreads();
    }

    const int tq = lane >> 2;
    const int tr = lane & 3;
#pragma unroll
    for (int mt = 0; mt < 2; ++mt) {
#pragma unroll
        for (int nt = 0; nt < 8; ++nt) {
            const int gcol = n0 + wn * 64 + nt * 8 + tr * 2;
            const float bv0 = bias[gcol];
            const float bv1 = bias[gcol + 1];
#pragma unroll
            for (int half = 0; half < 2; ++half) {
                const int grow = m0 + wm * 32 + mt * 16 + tq + half * 8;
                if (grow >= Mz) continue;
                float v0 = acc[mt][nt][half * 2 + 0] + bv0;
                float v1 = acc[mt][nt][half * 2 + 1] + bv1;
                if (QKV) {
                    int b = grow / Lz, l = grow - b * Lz;
                    int h = gcol >> 6, d = gcol & 63;
                    float* dst = (z == 0) ? g_Q : (z == 1) ? g_K : g_V;
                    *(float2*)(dst + (((size_t)(b * Hz + h)) * Lz + l) * Dz + d) =
                        make_float2(v0, v1);
                } else {
                    *(float2*)(Cout + (size_t)grow * Ez + gcol) = make_float2(v0, v1);
                }
            }
        }
    }
}

// ===========================================================================
// Fused attention: grid (40, Hz, Bz) x 256 threads.
//   bx in [0,32): windowed attention (LSU/ALU-optimized)
//   bx in [32,40): CLS split-K partials (two 128-thread groups)
// ===========================================================================
#define KPADF 68

__global__ __launch_bounds__(256) void attn_kernel()
{
    const int bx = blockIdx.x;
    const int h  = blockIdx.y;
    const int b  = blockIdx.z;
    const int tid = threadIdx.x;
    const unsigned FULL = 0xffffffffu;

    __shared__ float Ks[65][KPADF];
    __shared__ float Vs[65][64];
    __shared__ float Qs[32][64];
    // CLS path shared (per 128-thread group)
    __shared__ float c_qv[2][Dz];
    __shared__ float c_sc[2][CKEYS];
    __shared__ float c_redm[2][4];
    __shared__ float c_reds[2][4];
    __shared__ float c_oacc[2][2][Dz];

    const size_t bhbase = ((size_t)(b * Hz + h)) * Lz * Dz;

    if (bx < 32) {
        // ---------------- windowed path ----------------
        const int q0 = 1 + bx * 32;
        const float* Kbase = g_K + bhbase;
        const float* Vbase = g_V + bhbase;

        for (int i = tid; i < 65 * 16; i += 256) {
            int r = i >> 4;
            int c = (i & 15) * 4;
            int kidx = (r == 64) ? 0 : (q0 - 16 + r);
            float4 kv = make_float4(0.f, 0.f, 0.f, 0.f);
            float4 vv = kv;
            if (kidx >= 0 && kidx < Lz) {
                kv = *(const float4*)(Kbase + (size_t)kidx * Dz + c);
                vv = *(const float4*)(Vbase + (size_t)kidx * Dz + c);
            }
            *(float4*)&Ks[r][c] = kv;
            *(float4*)&Vs[r][c] = vv;
        }
        for (int i = tid; i < 32 * 16; i += 256) {
            int r = i >> 4;
            int c = (i & 15) * 4;
            *(float4*)&Qs[r][c] =
                *(const float4*)(g_Q + bhbase + (size_t)(q0 + r) * Dz + c);
        }
        __syncthreads();

        const int warp = tid >> 5;
        const int lane = tid & 31;
        const int base0 = warp * 4;

        float pq[4], phi[4], inv[4];

#pragma unroll
        for (int i = 0; i < 4; ++i) {
            const int ql = base0 + i;
            const int l  = q0 + ql;
            const int row = ql + lane;

            float s0 = 0.f, s1 = 0.f, s2 = 0.f, s3 = 0.f;
#pragma unroll
            for (int dg = 0; dg < 16; ++dg) {
                float4 q4 = *(const float4*)&Qs[ql][dg * 4];
                float4 k4 = *(const float4*)&Ks[row][dg * 4];
                s0 = fmaf(q4.x, k4.x, s0);
                s1 = fmaf(q4.y, k4.y, s1);
                s2 = fmaf(q4.z, k4.z, s2);
                s3 = fmaf(q4.w, k4.w, s3);
            }
            float sv = (s0 + s1) + (s2 + s3);

            // extra scores (w=32 on lane0, CLS on lane1) — only 2 lanes load
            float tv = 0.f;
            if (lane < 2) {
                const int row2 = (lane == 0) ? (ql + 32) : 64;
                float t0 = 0.f, t1 = 0.f, t2 = 0.f, t3 = 0.f;
#pragma unroll
                for (int dg = 0; dg < 16; ++dg) {
                    float4 q4  = *(const float4*)&Qs[ql][dg * 4];
                    float4 k24 = *(const float4*)&Ks[row2][dg * 4];
                    t0 = fmaf(q4.x, k24.x, t0);
                    t1 = fmaf(q4.y, k24.y, t1);
                    t2 = fmaf(q4.z, k24.z, t2);
                    t3 = fmaf(q4.w, k24.w, t3);
                }
                tv = (t0 + t1) + (t2 + t3);
            }

            const int kidx = l - PADz + lane;
            float s_lo = (kidx >= 1 && kidx < Lz) ? sv * SCALE : -INFINITY;
            float s_hi = -INFINITY;
            if (lane == 0) s_hi = (l + PADz < Lz) ? tv * SCALE : -INFINITY;
            if (lane == 1) s_hi = tv * SCALE;

            float m = fmaxf(s_lo, s_hi);
            m = fmaxf(m, __shfl_xor_sync(FULL, m, 16));
            m = fmaxf(m, __shfl_xor_sync(FULL, m, 8));
            m = fmaxf(m, __shfl_xor_sync(FULL, m, 4));
            m = fmaxf(m, __shfl_xor_sync(FULL, m, 2));
            m = fmaxf(m, __shfl_xor_sync(FULL, m, 1));

            float p  = __expf(s_lo - m);
            float ph = (lane < 2) ? __expf(s_hi - m) : 0.f;
            float t = p + ph;
            t += __shfl_xor_sync(FULL, t, 16);
            t += __shfl_xor_sync(FULL, t, 8);
            t += __shfl_xor_sync(FULL, t, 4);
            t += __shfl_xor_sync(FULL, t, 2);
            t += __shfl_xor_sync(FULL, t, 1);

            pq[i]  = p;
            phi[i] = ph;
            inv[i] = 1.f / t;
        }

        // ---- V accumulation: edge-split union pass ----
        float a0[4] = {0.f, 0.f, 0.f, 0.f};
        float a1[4] = {0.f, 0.f, 0.f, 0.f};

        // prologue: j = 0..2 (only queries i <= j valid, w = j-i in [0,2])
#pragma unroll
        for (int j = 0; j < 3; ++j) {
            const float v0 = Vs[base0 + j][lane];
            const float v1 = Vs[base0 + j][lane + 32];
#pragma unroll
            for (int i = 0; i <= j; ++i) {
                float pp = __shfl_sync(FULL, pq[i], j - i);
                a0[i] = fmaf(pp, v0, a0[i]);
                a1[i] = fmaf(pp, v1, a1[i]);
            }
        }
        // main: j = 3..31 — all 4 queries valid, compile-time lanes
#pragma unroll
        for (int j = 3; j < 32; ++j) {
            const float v0 = Vs[base0 + j][lane];
            const float v1 = Vs[base0 + j][lane + 32];
#pragma unroll
            for (int i = 0; i < 4; ++i) {
                float pp = __shfl_sync(FULL, pq[i], j - i);
                a0[i] = fmaf(pp, v0, a0[i]);
                a1[i] = fmaf(pp, v1, a1[i]);
            }
        }
        // epilogue: j = 32..35 (w = j-i in [28,32]; w==32 -> phi lane 0)
#pragma unroll
        for (int j = 32; j < 36; ++j) {
            const float v0 = Vs[base0 + j][lane];
            const float v1 = Vs[base0 + j][lane + 32];
#pragma unroll
            for (int i = 0; i < 4; ++i) {
                const int w = j - i;
                if (w > 32) continue;
                float pp = (w == 32) ? __shfl_sync(FULL, phi[i], 0)
                                     : __shfl_sync(FULL, pq[i], w);
                a0[i] = fmaf(pp, v0, a0[i]);
                a1[i] = fmaf(pp, v1, a1[i]);
            }
        }
        {   // CLS row
            const float v0 = Vs[64][lane];
            const float v1 = Vs[64][lane + 32];
#pragma unroll
            for (int i = 0; i < 4; ++i) {
                float pc = __shfl_sync(FULL, phi[i], 1);
                a0[i] = fmaf(pc, v0, a0[i]);
                a1[i] = fmaf(pc, v1, a1[i]);
            }
        }

#pragma unroll
        for (int i = 0; i < 4; ++i) {
            const int l = q0 + base0 + i;
            float o0 = a0[i] * inv[i];
            float o1 = a1[i] * inv[i];
            __nv_bfloat16 h0, l0, h1, l1;
            split1(o0, h0, l0);
            split1(o1, h1, l1);
            size_t o = ((size_t)b * Lz + l) * Ez + h * Dz;
            g_attn_hi[o + lane]      = h0;
            g_attn_lo[o + lane]      = l0;
            g_attn_hi[o + lane + 32] = h1;
            g_attn_lo[o + lane + 32] = l1;
        }
        __syncthreads();
        __syncthreads();
        __syncthreads();
    } else {
        // ---------------- CLS split-K path ----------------
        const int grpi = tid >> 7;
        const int gtid = tid & 127;
        const int warp = gtid >> 5;
        const int lane = tid & 31;
        const int sp = (bx - 32) * 2 + grpi;

        const int k0 = sp * CKEYS;
        const int nk = min(CKEYS, Lz - k0);

        if (gtid < Dz) c_qv[grpi][gtid] = g_Q[bhbase + gtid];
        __syncthreads();

        float lmax = -INFINITY;
        for (int i = warp; i < nk; i += 4) {
            const float* kr = g_K + bhbase + (size_t)(k0 + i) * Dz;
            float v = c_qv[grpi][lane] * kr[lane] + c_qv[grpi][lane + 32] * kr[lane + 32];
            v += __shfl_xor_sync(FULL, v, 16);
            v += __shfl_xor_sync(FULL, v, 8);
            v += __shfl_xor_sync(FULL, v, 4);
            v += __shfl_xor_sync(FULL, v, 2);
            v += __shfl_xor_sync(FULL, v, 1);
            v *= SCALE;
            if (lane == 0) c_sc[grpi][i] = v;
            lmax = fmaxf(lmax, v);
        }
        if (lane == 0) c_redm[grpi][warp] = lmax;
        __syncthreads();
        const float m = fmaxf(fmaxf(c_redm[grpi][0], c_redm[grpi][1]),
                              fmaxf(c_redm[grpi][2], c_redm[grpi][3]));

        float ls = 0.f;
        for (int i = gtid; i < nk; i += 128) {
            float p = __expf(c_sc[grpi][i] - m);
            c_sc[grpi][i] = p;
            ls += p;
        }
        ls += __shfl_xor_sync(FULL, ls, 16);
        ls += __shfl_xor_sync(FULL, ls, 8);
        ls += __shfl_xor_sync(FULL, ls, 4);
        ls += __shfl_xor_sync(FULL, ls, 2);
        ls += __shfl_xor_sync(FULL, ls, 1);
        if (lane == 0) c_reds[grpi][warp] = ls;
        __syncthreads();
        const float S = c_reds[grpi][0] + c_reds[grpi][1] +
                        c_reds[grpi][2] + c_reds[grpi][3];

        const int g = gtid >> 6;
        const int d = gtid & 63;
        float a = 0.f;
        for (int i = g; i < nk; i += 2)
            a = fmaf(c_sc[grpi][i], g_V[bhbase + (size_t)(k0 + i) * Dz + d], a);
        c_oacc[grpi][g][d] = a;
        __syncthreads();

        if (gtid < Dz) {
            const int idx = (b * Hz + h) * CSPL + sp;
            g_cls_o[(size_t)idx * Dz + gtid] = c_oacc[grpi][0][gtid] + c_oacc[grpi][1][gtid];
            if (gtid == 0) { g_cls_m[idx] = m; g_cls_s[idx] = S; }
        }
    }
}

// ---------------------------------------------------------------------------
// CLS combine: grid (Hz, Bz), 64 threads.
// ---------------------------------------------------------------------------
__global__ __launch_bounds__(64) void cls_comb_kernel()
{
    const int h = blockIdx.x;
    const int b = blockIdx.y;
    const int d = threadIdx.x;
    const int base = (b * Hz + h) * CSPL;

    float M = -INFINITY;
#pragma unroll
    for (int j = 0; j < CSPL; ++j) M = fmaxf(M, g_cls_m[base + j]);
    float S = 0.f, o = 0.f;
#pragma unroll
    for (int j = 0; j < CSPL; ++j) {
        float w = __expf(g_cls_m[base + j] - M);
        S = fmaf(g_cls_s[base + j], w, S);
        o = fmaf(g_cls_o[(size_t)(base + j) * Dz + d], w, o);
    }
    float acc = o / S;
    __nv_bfloat16 hh, ll;
    split1(acc, hh, ll);
    size_t off = ((size_t)b * Lz) * Ez + h * Dz + d;
    g_attn_hi[off] = hh;
    g_attn_lo[off] = ll;
}

// ---------------------------------------------------------------------------
// Launch
// ---------------------------------------------------------------------------
extern "C" void kernel_launch(void* const* d_in, const int* in_sizes, int n_in,
                              void* d_out, int out_size)
{
    const float* x  = (const float*)d_in[0];
    const float* Wq = (const float*)d_in[1];
    const float* bq = (const float*)d_in[2];
    const float* Wk = (const float*)d_in[3];
    const float* bk = (const float*)d_in[4];
    const float* Wv = (const float*)d_in[5];
    const float* bv = (const float*)d_in[6];
    const float* Wo = (const float*)d_in[7];
    const float* bo = (const float*)d_in[8];
    float* out = (float*)d_out;

    static bool attr_done = false;
    if (!attr_done) {
        cudaFuncSetAttribute((const void*)mma_gemm_kernel<1>,
                             cudaFuncAttributeMaxDynamicSharedMemorySize, 2 * STG_B);
        cudaFuncSetAttribute((const void*)mma_gemm_kernel<0>,
                             cudaFuncAttributeMaxDynamicSharedMemorySize, 2 * STG_B);
        attr_done = true;
    }

    prep_x_kernel<<<(Mz * Ez / 4 + 255) / 256, 256>>>(x);
    prep_w_kernel<<<dim3((WSZ + 255) / 256, 4), 256>>>(Wq, Wk, Wv, Wo);

    dim3 gridQKV(Ez / 128, (Mz + 127) / 128, 3);   // 585 CTAs
    dim3 gridO(Ez / 128, (Mz + 127) / 128);        // 195 CTAs

    mma_gemm_kernel<1><<<gridQKV, 256, 2 * STG_B>>>(bq, bk, bv, bo, nullptr);

    attn_kernel<<<dim3(40, Hz, Bz), 256>>>();      // window + CLS partials fused
    cls_comb_kernel<<<dim3(Hz, Bz), 64>>>();

    mma_gemm_kernel<0><<<gridO, 256, 2 * STG_B>>>(bq, bk, bv, bo, out);
}